// round 1
// baseline (speedup 1.0000x reference)
#include <cuda_runtime.h>
#include <math.h>

#define HEADS 8
#define DIM   64
#define BM    64
#define BN    64
#define LDP   65          // smem row stride (odd -> conflict-light)
#define NTHREADS 128

// Dynamic smem layout: Qs | Ks | Vs | Ps | rs | re
#define SMEM_FLOATS (4 * BM * LDP)
#define SMEM_BYTES  (SMEM_FLOATS * 4 + 2 * BM * 4)

__global__ __launch_bounds__(NTHREADS)
void attn_varlen_kernel(const float* __restrict__ qkv,
                        const int*   __restrict__ cu,
                        int nseg, int T,
                        float* __restrict__ out)
{
    extern __shared__ float smem[];
    float* Qs = smem;                    // [BM][LDP]
    float* Ks = Qs + BM * LDP;           // [BN][LDP]
    float* Vs = Ks + BN * LDP;           // [BN][LDP]
    float* Ps = Vs + BN * LDP;           // [BM][LDP]
    int*   rs = (int*)(Ps + BM * LDP);   // [BM] row kv start
    int*   re = rs + BM;                 // [BM] row kv end

    const int qt  = blockIdx.x;
    const int h   = blockIdx.y;
    const int q0  = qt * BM;
    const int tid = threadIdx.x;
    const int tstride = 3 * HEADS * DIM; // 1536 floats per token

    const float scale = 1.0f / sqrtf((float)DIM);

    const float* qbase = qkv + h * DIM;                    // qkv[t][0][h][:]
    const float* kbase = qkv + HEADS * DIM + h * DIM;      // qkv[t][1][h][:]
    const float* vbase = qkv + 2 * HEADS * DIM + h * DIM;  // qkv[t][2][h][:]

    // ---- load Q tile (pre-scaled) ----
    for (int e = tid; e < BM * (DIM / 4); e += NTHREADS) {
        int r  = e / (DIM / 4);
        int c4 = e % (DIM / 4);
        int t  = q0 + r;
        float4 v = make_float4(0.f, 0.f, 0.f, 0.f);
        if (t < T) v = *(const float4*)(qbase + (size_t)t * tstride + c4 * 4);
        Qs[r * LDP + c4 * 4 + 0] = v.x * scale;
        Qs[r * LDP + c4 * 4 + 1] = v.y * scale;
        Qs[r * LDP + c4 * 4 + 2] = v.z * scale;
        Qs[r * LDP + c4 * 4 + 3] = v.w * scale;
    }
    // ---- per-row segment bounds ----
    if (tid < BM) {
        int t = q0 + tid;
        int tc = t < T ? t : (T - 1);
        int s = 0;
        for (int i = 0; i < nseg; i++)
            if (tc >= cu[i]) s = i;
        rs[tid] = cu[s];
        re[tid] = cu[s + 1];
    }
    __syncthreads();

    const int kv_lo = rs[0];
    const int kv_hi = re[BM - 1];

    const int ig     = tid >> 4;      // 0..7 : row group of 8
    const int lane16 = tid & 15;      // 0..15: column / d-chunk group
    const int i0     = ig * 8;
    const int d0     = lane16 * 4;    // also the S-column base within the tile

    float m[8], l[8], acc[8][4];
    #pragma unroll
    for (int r = 0; r < 8; r++) {
        m[r] = -1e30f; l[r] = 0.f;
        #pragma unroll
        for (int d = 0; d < 4; d++) acc[r][d] = 0.f;
    }

    for (int kb = kv_lo; kb < kv_hi; kb += BN) {
        // ---- load K,V tiles ----
        for (int e = tid; e < BN * (DIM / 4); e += NTHREADS) {
            int r  = e / (DIM / 4);
            int c4 = e % (DIM / 4);
            int t  = kb + r;
            float4 kv = make_float4(0.f, 0.f, 0.f, 0.f);
            if (t < kv_hi && t < T) kv = *(const float4*)(kbase + (size_t)t * tstride + c4 * 4);
            Ks[r * LDP + c4 * 4 + 0] = kv.x;
            Ks[r * LDP + c4 * 4 + 1] = kv.y;
            Ks[r * LDP + c4 * 4 + 2] = kv.z;
            Ks[r * LDP + c4 * 4 + 3] = kv.w;
            float4 vv = make_float4(0.f, 0.f, 0.f, 0.f);
            if (t < kv_hi && t < T) vv = *(const float4*)(vbase + (size_t)t * tstride + c4 * 4);
            Vs[r * LDP + c4 * 4 + 0] = vv.x;
            Vs[r * LDP + c4 * 4 + 1] = vv.y;
            Vs[r * LDP + c4 * 4 + 2] = vv.z;
            Vs[r * LDP + c4 * 4 + 3] = vv.w;
        }
        __syncthreads();

        // ---- S = Q K^T  (thread: rows i0..i0+7, cols d0..d0+3) ----
        float s[8][4];
        #pragma unroll
        for (int r = 0; r < 8; r++)
            #pragma unroll
            for (int j = 0; j < 4; j++) s[r][j] = 0.f;

        #pragma unroll 8
        for (int d = 0; d < DIM; d++) {
            float kvr[4];
            #pragma unroll
            for (int j = 0; j < 4; j++) kvr[j] = Ks[(d0 + j) * LDP + d];
            #pragma unroll
            for (int r = 0; r < 8; r++) {
                float qv = Qs[(i0 + r) * LDP + d];
                #pragma unroll
                for (int j = 0; j < 4; j++) s[r][j] = fmaf(qv, kvr[j], s[r][j]);
            }
        }

        // ---- mask + online softmax ----
        #pragma unroll
        for (int r = 0; r < 8; r++) {
            const int row = i0 + r;
            const int rstart = rs[row], rend = re[row];
            float tmax = -1e30f;
            bool valid[4];
            #pragma unroll
            for (int j = 0; j < 4; j++) {
                int kvpos = kb + d0 + j;
                valid[j] = (kvpos >= rstart) && (kvpos < rend);
                if (!valid[j]) s[r][j] = -1e30f;
                tmax = fmaxf(tmax, s[r][j]);
            }
            #pragma unroll
            for (int o = 1; o < 16; o <<= 1)
                tmax = fmaxf(tmax, __shfl_xor_sync(0xffffffffu, tmax, o));

            float mnew  = fmaxf(m[r], tmax);
            float alpha = __expf(m[r] - mnew);
            float psum  = 0.f;
            #pragma unroll
            for (int j = 0; j < 4; j++) {
                float p = valid[j] ? __expf(s[r][j] - mnew) : 0.f;
                s[r][j] = p;
                psum += p;
            }
            #pragma unroll
            for (int o = 1; o < 16; o <<= 1)
                psum += __shfl_xor_sync(0xffffffffu, psum, o);

            l[r] = l[r] * alpha + psum;
            m[r] = mnew;
            #pragma unroll
            for (int d = 0; d < 4; d++) acc[r][d] *= alpha;
            #pragma unroll
            for (int j = 0; j < 4; j++) Ps[row * LDP + d0 + j] = s[r][j];
        }
        __syncthreads();

        // ---- O += P @ V  (thread: rows i0..i0+7, d-chunk d0..d0+3) ----
        #pragma unroll 8
        for (int j = 0; j < BN; j++) {
            float vv[4];
            #pragma unroll
            for (int d = 0; d < 4; d++) vv[d] = Vs[j * LDP + d0 + d];
            #pragma unroll
            for (int r = 0; r < 8; r++) {
                float p = Ps[(i0 + r) * LDP + j];
                #pragma unroll
                for (int d = 0; d < 4; d++) acc[r][d] = fmaf(p, vv[d], acc[r][d]);
            }
        }
        __syncthreads();
    }

    // ---- epilogue: normalize + store ----
    const int ostride = HEADS * DIM;
    #pragma unroll
    for (int r = 0; r < 8; r++) {
        int t = q0 + i0 + r;
        if (t >= T) continue;
        float inv = (l[r] > 0.f) ? (1.f / l[r]) : 0.f;
        float4 o;
        o.x = acc[r][0] * inv;
        o.y = acc[r][1] * inv;
        o.z = acc[r][2] * inv;
        o.w = acc[r][3] * inv;
        *(float4*)(out + (size_t)t * ostride + h * DIM + d0) = o;
    }
}

extern "C" void kernel_launch(void* const* d_in, const int* in_sizes, int n_in,
                              void* d_out, int out_size)
{
    const float* qkv = (const float*)d_in[0];
    const int*   cu  = (const int*)d_in[1];
    const int ncu  = in_sizes[1];
    const int nseg = ncu - 1;
    const int T    = in_sizes[0] / (3 * HEADS * DIM);

    static bool attr_set = false;
    if (!attr_set) {
        cudaFuncSetAttribute(attn_varlen_kernel,
                             cudaFuncAttributeMaxDynamicSharedMemorySize,
                             SMEM_BYTES);
        attr_set = true;
    }

    dim3 grid((T + BM - 1) / BM, HEADS);
    attn_varlen_kernel<<<grid, NTHREADS, SMEM_BYTES>>>(
        qkv, cu, nseg, T, (float*)d_out);
}

// round 3
// speedup vs baseline: 2.3911x; 2.3911x over previous
#include <cuda_runtime.h>
#include <cuda_bf16.h>
#include <cstdint>

#define HEADS 8
#define DIM   64
#define TMAXP 4096
#define BM    128
#define BN    64
#define NT    256
#define LDE   72            // bf16 elems per smem row (pad 64+8)
#define LDBY  144           // bytes per smem row

// smem layout (bytes)
#define S_QH 0
#define S_QL (S_QH + BM * LDBY)          // 18432
#define S_KH (S_QL + BM * LDBY)          // 36864
#define S_KL (S_KH + BN * LDBY)          // 46080
#define S_VH (S_KL + BN * LDBY)          // 55296
#define S_VL (S_VH + BN * LDBY)          // 64512
#define S_RS (S_VL + BN * LDBY)          // 73728
#define S_RE (S_RS + BM * 4)
#define SMEM_BYTES (S_RE + BM * 4)       // 74752

// ---------------- scratch ----------------
__device__ __nv_bfloat16 g_Qh[(size_t)HEADS * TMAXP * DIM];
__device__ __nv_bfloat16 g_Ql[(size_t)HEADS * TMAXP * DIM];
__device__ __nv_bfloat16 g_Kh[(size_t)HEADS * TMAXP * DIM];
__device__ __nv_bfloat16 g_Kl[(size_t)HEADS * TMAXP * DIM];
__device__ __nv_bfloat16 g_Vh[(size_t)HEADS * TMAXP * DIM];
__device__ __nv_bfloat16 g_Vl[(size_t)HEADS * TMAXP * DIM];

// ---------------- helpers ----------------
__device__ __forceinline__ uint32_t smem_u32(const void* p) {
    uint32_t a;
    asm("{ .reg .u64 t; cvta.to.shared.u64 t, %1; cvt.u32.u64 %0, t; }" : "=r"(a) : "l"(p));
    return a;
}
__device__ __forceinline__ void ldsm_x4(uint32_t& r0, uint32_t& r1, uint32_t& r2, uint32_t& r3, uint32_t a) {
    asm volatile("ldmatrix.sync.aligned.m8n8.x4.shared.b16 {%0,%1,%2,%3}, [%4];"
                 : "=r"(r0), "=r"(r1), "=r"(r2), "=r"(r3) : "r"(a));
}
__device__ __forceinline__ void ldsm_x2(uint32_t& r0, uint32_t& r1, uint32_t a) {
    asm volatile("ldmatrix.sync.aligned.m8n8.x2.shared.b16 {%0,%1}, [%2];"
                 : "=r"(r0), "=r"(r1) : "r"(a));
}
__device__ __forceinline__ void ldsm_x2t(uint32_t& r0, uint32_t& r1, uint32_t a) {
    asm volatile("ldmatrix.sync.aligned.m8n8.x2.trans.shared.b16 {%0,%1}, [%2];"
                 : "=r"(r0), "=r"(r1) : "r"(a));
}
__device__ __forceinline__ void mma_bf16(float* c, const uint32_t* a, const uint32_t* b) {
    asm volatile("mma.sync.aligned.m16n8k16.row.col.f32.bf16.bf16.f32 "
                 "{%0,%1,%2,%3}, {%4,%5,%6,%7}, {%8,%9}, {%0,%1,%2,%3};"
                 : "+f"(c[0]), "+f"(c[1]), "+f"(c[2]), "+f"(c[3])
                 : "r"(a[0]), "r"(a[1]), "r"(a[2]), "r"(a[3]), "r"(b[0]), "r"(b[1]));
}
// split pair of floats into packed bf16 hi + packed bf16 residual
__device__ __forceinline__ void split2(float a, float b, uint32_t& hi, uint32_t& lo) {
    uint32_t h;
    asm("cvt.rn.bf16x2.f32 %0, %1, %2;" : "=r"(h) : "f"(b), "f"(a));
    float ah = __uint_as_float(h << 16);
    float bh = __uint_as_float(h & 0xffff0000u);
    uint32_t l;
    float ar = a - ah, br = b - bh;
    asm("cvt.rn.bf16x2.f32 %0, %1, %2;" : "=r"(l) : "f"(br), "f"(ar));
    hi = h; lo = l;
}

// ---------------- prep: fp32 qkv -> bf16 hi/lo, head-major ----------------
__global__ void prep(const float* __restrict__ qkv, int T) {
    int idx = blockIdx.x * blockDim.x + threadIdx.x;
    if (idx >= T * HEADS * 16) return;
    int d4 = idx & 15;
    int h  = (idx >> 4) & (HEADS - 1);
    int t  = idx >> 7;
    const size_t gin = (size_t)t * 1536 + h * 64 + d4 * 4;
    const float4 q = *(const float4*)(qkv + gin);
    const float4 k = *(const float4*)(qkv + gin + 512);
    const float4 v = *(const float4*)(qkv + gin + 1024);
    size_t base = ((size_t)h * TMAXP + t) * DIM + d4 * 4;
    const float s = 0.125f; // 1/sqrt(64)
    uint32_t h0, l0, h1, l1;
    split2(q.x * s, q.y * s, h0, l0); split2(q.z * s, q.w * s, h1, l1);
    *(uint2*)(g_Qh + base) = make_uint2(h0, h1);
    *(uint2*)(g_Ql + base) = make_uint2(l0, l1);
    split2(k.x, k.y, h0, l0); split2(k.z, k.w, h1, l1);
    *(uint2*)(g_Kh + base) = make_uint2(h0, h1);
    *(uint2*)(g_Kl + base) = make_uint2(l0, l1);
    split2(v.x, v.y, h0, l0); split2(v.z, v.w, h1, l1);
    *(uint2*)(g_Vh + base) = make_uint2(h0, h1);
    *(uint2*)(g_Vl + base) = make_uint2(l0, l1);
}

// ---------------- main attention ----------------
__global__ __launch_bounds__(NT)
void attn_main(const int* __restrict__ cu, int nseg, int T, float* __restrict__ out)
{
    extern __shared__ char smem[];
    const uint32_t sb = smem_u32(smem);
    const int tid = threadIdx.x, wid = tid >> 5, lane = tid & 31;
    const int q0 = blockIdx.x * BM;
    const int h  = blockIdx.y;
    int* rs_s = (int*)(smem + S_RS);
    int* re_s = (int*)(smem + S_RE);

    // stage Q tile (hi/lo)
    {
        const uint4* qh = (const uint4*)(g_Qh + ((size_t)h * TMAXP + q0) * DIM);
        const uint4* ql = (const uint4*)(g_Ql + ((size_t)h * TMAXP + q0) * DIM);
        #pragma unroll
        for (int i = tid; i < BM * 8; i += NT) {
            int row = i >> 3, c = i & 7;
            uint32_t soff = row * LDBY + c * 16;
            if (q0 + row < T) {
                *(uint4*)(smem + S_QH + soff) = qh[i];
                *(uint4*)(smem + S_QL + soff) = ql[i];
            } else {
                const uint4 z = make_uint4(0, 0, 0, 0);
                *(uint4*)(smem + S_QH + soff) = z;
                *(uint4*)(smem + S_QL + soff) = z;
            }
        }
    }
    // per-row segment bounds
    if (tid < BM) {
        int t = q0 + tid; if (t > T - 1) t = T - 1;
        int s = 0;
        for (int i = 0; i < nseg; i++) if (t >= cu[i]) s = i;
        rs_s[tid] = cu[s]; re_s[tid] = cu[s + 1];
    }
    __syncthreads();
    const int kvlo = rs_s[0];
    const int kvhi = re_s[BM - 1];

    const int m0 = wid * 16;
    const int r0 = m0 + (lane >> 2);
    const int lo0 = rs_s[r0],     hi0 = re_s[r0];
    const int lo1 = rs_s[r0 + 8], hi1 = re_s[r0 + 8];

    float m0r = -1e30f, m1r = -1e30f, l0r = 0.f, l1r = 0.f;
    float o[8][4];
    #pragma unroll
    for (int n = 0; n < 8; n++)
        #pragma unroll
        for (int e = 0; e < 4; e++) o[n][e] = 0.f;

    // fragment smem addresses (lane-dependent, loop-invariant parts)
    const uint32_t qa = sb + S_QH + (m0 + (lane & 15)) * LDBY + ((lane >> 4) * 8) * 2;
    const uint32_t ka = sb + S_KH + (lane & 7) * LDBY + (((lane >> 3) & 1) * 8) * 2;
    const uint32_t va = sb + S_VH + (lane & 15) * LDBY;

    for (int kb = kvlo; kb < kvhi; kb += BN) {
        // ---- stage K/V tiles (hi/lo), zero-pad past kvhi ----
        {
            const uint4* kh = (const uint4*)(g_Kh + ((size_t)h * TMAXP + kb) * DIM);
            const uint4* kl = (const uint4*)(g_Kl + ((size_t)h * TMAXP + kb) * DIM);
            const uint4* vh = (const uint4*)(g_Vh + ((size_t)h * TMAXP + kb) * DIM);
            const uint4* vl = (const uint4*)(g_Vl + ((size_t)h * TMAXP + kb) * DIM);
            #pragma unroll
            for (int i = tid; i < BN * 8; i += NT) {
                int row = i >> 3, c = i & 7;
                uint32_t soff = row * LDBY + c * 16;
                if (kb + row < kvhi) {
                    *(uint4*)(smem + S_KH + soff) = kh[i];
                    *(uint4*)(smem + S_KL + soff) = kl[i];
                    *(uint4*)(smem + S_VH + soff) = vh[i];
                    *(uint4*)(smem + S_VL + soff) = vl[i];
                } else {
                    const uint4 z = make_uint4(0, 0, 0, 0);
                    *(uint4*)(smem + S_KH + soff) = z;
                    *(uint4*)(smem + S_KL + soff) = z;
                    *(uint4*)(smem + S_VH + soff) = z;
                    *(uint4*)(smem + S_VL + soff) = z;
                }
            }
        }
        __syncthreads();

        // ---- MMA1: S = Qh Kh^T + Ql Kh^T + Qh Kl^T ----
        float s[8][4];
        #pragma unroll
        for (int n = 0; n < 8; n++)
            #pragma unroll
            for (int e = 0; e < 4; e++) s[n][e] = 0.f;

        #pragma unroll
        for (int c = 0; c < 4; c++) {
            uint32_t qh[4], ql[4];
            ldsm_x4(qh[0], qh[1], qh[2], qh[3], qa + c * 32);
            ldsm_x4(ql[0], ql[1], ql[2], ql[3], qa + c * 32 + (S_QL - S_QH));
            #pragma unroll
            for (int j = 0; j < 8; j++) {
                uint32_t kh[2], kl[2];
                uint32_t kaddr = ka + j * 8 * LDBY + c * 32;
                ldsm_x2(kh[0], kh[1], kaddr);
                ldsm_x2(kl[0], kl[1], kaddr + (S_KL - S_KH));
                mma_bf16(s[j], qh, kh);
                mma_bf16(s[j], ql, kh);
                mma_bf16(s[j], qh, kl);
            }
        }

        // ---- masked online softmax (per-thread: rows r0, r0+8) ----
        const int clo0 = lo0 - kb, chi0 = hi0 - kb;
        const int clo1 = lo1 - kb, chi1 = hi1 - kb;
        float mt0 = -1e30f, mt1 = -1e30f;
        #pragma unroll
        for (int j = 0; j < 8; j++) {
            int cb = j * 8 + (lane & 3) * 2;
            bool v0a = cb >= clo0 && cb < chi0, v0b = cb + 1 >= clo0 && cb + 1 < chi0;
            bool v1a = cb >= clo1 && cb < chi1, v1b = cb + 1 >= clo1 && cb + 1 < chi1;
            if (v0a) mt0 = fmaxf(mt0, s[j][0]);
            if (v0b) mt0 = fmaxf(mt0, s[j][1]);
            if (v1a) mt1 = fmaxf(mt1, s[j][2]);
            if (v1b) mt1 = fmaxf(mt1, s[j][3]);
        }
        mt0 = fmaxf(mt0, __shfl_xor_sync(0xffffffffu, mt0, 1));
        mt0 = fmaxf(mt0, __shfl_xor_sync(0xffffffffu, mt0, 2));
        mt1 = fmaxf(mt1, __shfl_xor_sync(0xffffffffu, mt1, 1));
        mt1 = fmaxf(mt1, __shfl_xor_sync(0xffffffffu, mt1, 2));

        float mn0 = fmaxf(m0r, mt0), mn1 = fmaxf(m1r, mt1);
        float a0 = __expf(m0r - mn0), a1 = __expf(m1r - mn1);
        m0r = mn0; m1r = mn1;
        #pragma unroll
        for (int n = 0; n < 8; n++) {
            o[n][0] *= a0; o[n][1] *= a0;
            o[n][2] *= a1; o[n][3] *= a1;
        }

        uint32_t ph[8][2], pl[8][2];
        float ps0 = 0.f, ps1 = 0.f;
        #pragma unroll
        for (int j = 0; j < 8; j++) {
            int cb = j * 8 + (lane & 3) * 2;
            float p0 = (cb >= clo0 && cb < chi0)         ? __expf(s[j][0] - mn0) : 0.f;
            float p1 = (cb + 1 >= clo0 && cb + 1 < chi0) ? __expf(s[j][1] - mn0) : 0.f;
            float p2 = (cb >= clo1 && cb < chi1)         ? __expf(s[j][2] - mn1) : 0.f;
            float p3 = (cb + 1 >= clo1 && cb + 1 < chi1) ? __expf(s[j][3] - mn1) : 0.f;
            ps0 += p0 + p1; ps1 += p2 + p3;
            split2(p0, p1, ph[j][0], pl[j][0]);
            split2(p2, p3, ph[j][1], pl[j][1]);
        }
        l0r = l0r * a0 + ps0;
        l1r = l1r * a1 + ps1;

        // ---- MMA2: O += Ph Vh + Pl Vh + Ph Vl ----
        #pragma unroll
        for (int c = 0; c < 4; c++) {
            uint32_t pah[4] = { ph[2*c][0], ph[2*c][1], ph[2*c+1][0], ph[2*c+1][1] };
            uint32_t pal[4] = { pl[2*c][0], pl[2*c][1], pl[2*c+1][0], pl[2*c+1][1] };
            #pragma unroll
            for (int n = 0; n < 8; n++) {
                uint32_t vh[2], vl[2];
                uint32_t vaddr = va + c * 16 * LDBY + n * 16;
                ldsm_x2t(vh[0], vh[1], vaddr);
                ldsm_x2t(vl[0], vl[1], vaddr + (S_VL - S_VH));
                mma_bf16(o[n], pah, vh);
                mma_bf16(o[n], pal, vh);
                mma_bf16(o[n], pah, vl);
            }
        }
        __syncthreads();
    }

    // ---- epilogue ----
    l0r += __shfl_xor_sync(0xffffffffu, l0r, 1);
    l0r += __shfl_xor_sync(0xffffffffu, l0r, 2);
    l1r += __shfl_xor_sync(0xffffffffu, l1r, 1);
    l1r += __shfl_xor_sync(0xffffffffu, l1r, 2);
    float inv0 = l0r > 0.f ? 1.f / l0r : 0.f;
    float inv1 = l1r > 0.f ? 1.f / l1r : 0.f;

    const int t0 = q0 + r0, t1 = t0 + 8;
    const int colb = (lane & 3) * 2;
    if (t0 < T) {
        float* op = out + (size_t)t0 * (HEADS * DIM) + h * DIM + colb;
        #pragma unroll
        for (int n = 0; n < 8; n++)
            *(float2*)(op + n * 8) = make_float2(o[n][0] * inv0, o[n][1] * inv0);
    }
    if (t1 < T) {
        float* op = out + (size_t)t1 * (HEADS * DIM) + h * DIM + colb;
        #pragma unroll
        for (int n = 0; n < 8; n++)
            *(float2*)(op + n * 8) = make_float2(o[n][2] * inv1, o[n][3] * inv1);
    }
}

// ---------------- launch ----------------
extern "C" void kernel_launch(void* const* d_in, const int* in_sizes, int n_in,
                              void* d_out, int out_size)
{
    const float* qkv = (const float*)d_in[0];
    const int*   cu  = (const int*)d_in[1];
    const int T    = in_sizes[0] / (3 * HEADS * DIM);
    const int nseg = in_sizes[1] - 1;

    static bool init = false;
    if (!init) {
        cudaFuncSetAttribute(attn_main, cudaFuncAttributeMaxDynamicSharedMemorySize, SMEM_BYTES);
        init = true;
    }

    prep<<<(T * HEADS * 16 + 255) / 256, 256>>>(qkv, T);
    attn_main<<<dim3((T + BM - 1) / BM, HEADS), NT, SMEM_BYTES>>>(cu, nseg, T, (float*)d_out);
}

// round 4
// speedup vs baseline: 2.9749x; 1.2441x over previous
#include <cuda_runtime.h>
#include <cuda_bf16.h>
#include <cstdint>

#define HEADS 8
#define DIM   64
#define TMAXP 4096
#define BM    128
#define BN    64
#define NT    256

// smem layout (bytes): swizzled 128B rows
#define S_QH 0
#define S_QL 16384
#define S_KV 32768            // + stage*KV_STAGE
#define KV_STAGE 32768
#define T_KH 0
#define T_KL 8192
#define T_VH 16384
#define T_VL 24576
#define S_RS 98304
#define S_RE 98816
#define SMEM_BYTES 99328

// ---------------- scratch ----------------
__device__ __align__(16) __nv_bfloat16 g_Qh[(size_t)HEADS * TMAXP * DIM];
__device__ __align__(16) __nv_bfloat16 g_Ql[(size_t)HEADS * TMAXP * DIM];
__device__ __align__(16) __nv_bfloat16 g_Kh[(size_t)HEADS * TMAXP * DIM];
__device__ __align__(16) __nv_bfloat16 g_Kl[(size_t)HEADS * TMAXP * DIM];
__device__ __align__(16) __nv_bfloat16 g_Vh[(size_t)HEADS * TMAXP * DIM];
__device__ __align__(16) __nv_bfloat16 g_Vl[(size_t)HEADS * TMAXP * DIM];

// ---------------- helpers ----------------
__device__ __forceinline__ uint32_t smem_u32(const void* p) {
    uint32_t a;
    asm("{ .reg .u64 t; cvta.to.shared.u64 t, %1; cvt.u32.u64 %0, t; }" : "=r"(a) : "l"(p));
    return a;
}
__device__ __forceinline__ void ldsm_x4(uint32_t& r0, uint32_t& r1, uint32_t& r2, uint32_t& r3, uint32_t a) {
    asm volatile("ldmatrix.sync.aligned.m8n8.x4.shared.b16 {%0,%1,%2,%3}, [%4];"
                 : "=r"(r0), "=r"(r1), "=r"(r2), "=r"(r3) : "r"(a));
}
__device__ __forceinline__ void ldsm_x2(uint32_t& r0, uint32_t& r1, uint32_t a) {
    asm volatile("ldmatrix.sync.aligned.m8n8.x2.shared.b16 {%0,%1}, [%2];"
                 : "=r"(r0), "=r"(r1) : "r"(a));
}
__device__ __forceinline__ void ldsm_x2t(uint32_t& r0, uint32_t& r1, uint32_t a) {
    asm volatile("ldmatrix.sync.aligned.m8n8.x2.trans.shared.b16 {%0,%1}, [%2];"
                 : "=r"(r0), "=r"(r1) : "r"(a));
}
__device__ __forceinline__ void mma_bf16(float* c, const uint32_t* a, const uint32_t* b) {
    asm volatile("mma.sync.aligned.m16n8k16.row.col.f32.bf16.bf16.f32 "
                 "{%0,%1,%2,%3}, {%4,%5,%6,%7}, {%8,%9}, {%0,%1,%2,%3};"
                 : "+f"(c[0]), "+f"(c[1]), "+f"(c[2]), "+f"(c[3])
                 : "r"(a[0]), "r"(a[1]), "r"(a[2]), "r"(a[3]), "r"(b[0]), "r"(b[1]));
}
__device__ __forceinline__ void split2(float a, float b, uint32_t& hi, uint32_t& lo) {
    uint32_t h;
    asm("cvt.rn.bf16x2.f32 %0, %1, %2;" : "=r"(h) : "f"(b), "f"(a));
    float ah = __uint_as_float(h << 16);
    float bh = __uint_as_float(h & 0xffff0000u);
    uint32_t l;
    float ar = a - ah, br = b - bh;
    asm("cvt.rn.bf16x2.f32 %0, %1, %2;" : "=r"(l) : "f"(br), "f"(ar));
    hi = h; lo = l;
}
#define CP_ASYNC(dst, src, sz) \
    asm volatile("cp.async.cg.shared.global [%0], [%1], 16, %2;" :: "r"(dst), "l"(src), "r"(sz))
#define CP_COMMIT() asm volatile("cp.async.commit_group;" ::: "memory")
#define CP_WAIT0()  asm volatile("cp.async.wait_group 0;" ::: "memory")
#define CP_WAIT1()  asm volatile("cp.async.wait_group 1;" ::: "memory")

// ---------------- prep: fp32 qkv -> bf16 hi/lo, head-major ----------------
__global__ void prep(const float* __restrict__ qkv, int T) {
    int idx = blockIdx.x * blockDim.x + threadIdx.x;
    if (idx >= T * HEADS * 16) return;
    int d4 = idx & 15;
    int h  = (idx >> 4) & (HEADS - 1);
    int t  = idx >> 7;
    const size_t gin = (size_t)t * 1536 + h * 64 + d4 * 4;
    const float4 q = *(const float4*)(qkv + gin);
    const float4 k = *(const float4*)(qkv + gin + 512);
    const float4 v = *(const float4*)(qkv + gin + 1024);
    size_t base = ((size_t)h * TMAXP + t) * DIM + d4 * 4;
    const float s = 0.125f;
    uint32_t h0, l0, h1, l1;
    split2(q.x * s, q.y * s, h0, l0); split2(q.z * s, q.w * s, h1, l1);
    *(uint2*)(g_Qh + base) = make_uint2(h0, h1);
    *(uint2*)(g_Ql + base) = make_uint2(l0, l1);
    split2(k.x, k.y, h0, l0); split2(k.z, k.w, h1, l1);
    *(uint2*)(g_Kh + base) = make_uint2(h0, h1);
    *(uint2*)(g_Kl + base) = make_uint2(l0, l1);
    split2(v.x, v.y, h0, l0); split2(v.z, v.w, h1, l1);
    *(uint2*)(g_Vh + base) = make_uint2(h0, h1);
    *(uint2*)(g_Vl + base) = make_uint2(l0, l1);
}

// ---------------- main attention ----------------
__global__ __launch_bounds__(NT, 2)
void attn_main(const int* __restrict__ cu, int nseg, int T, float* __restrict__ out)
{
    extern __shared__ char smem[];
    const uint32_t sb = smem_u32(smem);
    const int tid = threadIdx.x, wid = tid >> 5, lane = tid & 31;
    const int q0 = blockIdx.x * BM;
    const int h  = blockIdx.y;
    int* rs_s = (int*)(smem + S_RS);
    int* re_s = (int*)(smem + S_RE);

    // stage Q tile (hi/lo), swizzled
    {
        const uint4* qh = (const uint4*)(g_Qh + ((size_t)h * TMAXP + q0) * DIM);
        const uint4* ql = (const uint4*)(g_Ql + ((size_t)h * TMAXP + q0) * DIM);
        #pragma unroll
        for (int p = 0; p < 4; p++) {
            int i = tid + p * NT;
            int row = i >> 3, c = i & 7;
            uint32_t soff = (uint32_t)(row * 128 + ((c ^ (row & 7)) << 4));
            if (q0 + row < T) {
                *(uint4*)(smem + S_QH + soff) = qh[i];
                *(uint4*)(smem + S_QL + soff) = ql[i];
            } else {
                const uint4 z = make_uint4(0, 0, 0, 0);
                *(uint4*)(smem + S_QH + soff) = z;
                *(uint4*)(smem + S_QL + soff) = z;
            }
        }
    }
    if (tid < BM) {
        int t = q0 + tid; if (t > T - 1) t = T - 1;
        int s = 0;
        for (int i = 0; i < nseg; i++) if (t >= cu[i]) s = i;
        rs_s[tid] = cu[s]; re_s[tid] = cu[s + 1];
    }
    __syncthreads();
    const int kvlo = rs_s[0];
    const int kvhi = re_s[BM - 1];

    const int m0 = wid * 16;
    const int r0 = m0 + (lane >> 2);
    const int lo0 = rs_s[r0],     hi0 = re_s[r0];
    const int lo1 = rs_s[r0 + 8], hi1 = re_s[r0 + 8];

    // gmem K/V base pointers for this head
    const __nv_bfloat16* gKH = g_Kh + (size_t)h * TMAXP * DIM;
    const __nv_bfloat16* gKL = g_Kl + (size_t)h * TMAXP * DIM;
    const __nv_bfloat16* gVH = g_Vh + (size_t)h * TMAXP * DIM;
    const __nv_bfloat16* gVL = g_Vl + (size_t)h * TMAXP * DIM;

    // cp.async staging geometry: c fixed per thread, two rows per tile
    const int cpc   = tid & 7;
    const int cprow0 = tid >> 3;          // 0..31
    const int cprow1 = cprow0 + 32;       // 32..63
    const uint32_t cpoff0 = (uint32_t)(cprow0 * 128 + ((cpc ^ (cprow0 & 7)) << 4));
    const uint32_t cpoff1 = (uint32_t)(cprow1 * 128 + ((cpc ^ (cprow1 & 7)) << 4));
    const int cpg0 = cprow0 * 64 + cpc * 8;  // bf16 element offset
    const int cpg1 = cprow1 * 64 + cpc * 8;

    float m0r = -1e30f, m1r = -1e30f, l0r = 0.f, l1r = 0.f;
    float o[8][4];
    #pragma unroll
    for (int n = 0; n < 8; n++)
        #pragma unroll
        for (int e = 0; e < 4; e++) o[n][e] = 0.f;

    // fragment address invariants
    const int swz = lane & 7;
    const uint32_t qrow = (uint32_t)((m0 + (lane & 15)) * 128);
    const int qcc = lane >> 4;              // 0/1
    const uint32_t krow = (uint32_t)((lane & 7) * 128);
    const int kcc = (lane >> 3) & 1;
    const uint32_t vrow = (uint32_t)((lane & 15) * 128);

    const int nIter = (kvhi - kvlo + BN - 1) / BN;

    // prologue: stage tile 0 into buffer 0
    {
        const int kb = kvlo;
        #pragma unroll
        for (int t4 = 0; t4 < 4; t4++) {
            const __nv_bfloat16* g = (t4 == 0) ? gKH : (t4 == 1) ? gKL : (t4 == 2) ? gVH : gVL;
            uint32_t dbase = sb + S_KV + (uint32_t)(t4 * 8192);
            int sz0 = (kb + cprow0 < kvhi) ? 16 : 0;
            int sz1 = (kb + cprow1 < kvhi) ? 16 : 0;
            CP_ASYNC(dbase + cpoff0, g + (size_t)kb * DIM + cpg0, sz0);
            CP_ASYNC(dbase + cpoff1, g + (size_t)kb * DIM + cpg1, sz1);
        }
        CP_COMMIT();
    }

    for (int it = 0; it < nIter; it++) {
        const int kb = kvlo + it * BN;
        // issue next tile into other buffer, then wait for current
        if (it + 1 < nIter) {
            const int kn = kb + BN;
            uint32_t nbase = sb + S_KV + (uint32_t)(((it + 1) & 1) * KV_STAGE);
            #pragma unroll
            for (int t4 = 0; t4 < 4; t4++) {
                const __nv_bfloat16* g = (t4 == 0) ? gKH : (t4 == 1) ? gKL : (t4 == 2) ? gVH : gVL;
                uint32_t dbase = nbase + (uint32_t)(t4 * 8192);
                int sz0 = (kn + cprow0 < kvhi) ? 16 : 0;
                int sz1 = (kn + cprow1 < kvhi) ? 16 : 0;
                CP_ASYNC(dbase + cpoff0, g + (size_t)kn * DIM + cpg0, sz0);
                CP_ASYNC(dbase + cpoff1, g + (size_t)kn * DIM + cpg1, sz1);
            }
            CP_COMMIT();
            CP_WAIT1();
        } else {
            CP_WAIT0();
        }
        __syncthreads();

        const uint32_t kvb = sb + S_KV + (uint32_t)((it & 1) * KV_STAGE);
        const uint32_t kbase = kvb + T_KH + krow;
        const uint32_t vbase = kvb + T_VH + vrow;

        // ---- MMA1: S = Qh Kh^T + Ql Kh^T + Qh Kl^T ----
        float s[8][4];
        #pragma unroll
        for (int n = 0; n < 8; n++)
            #pragma unroll
            for (int e = 0; e < 4; e++) s[n][e] = 0.f;

        #pragma unroll
        for (int c = 0; c < 4; c++) {
            uint32_t qh[4], ql[4];
            uint32_t qaddr = sb + S_QH + qrow + (uint32_t)(((qcc + 2 * c) ^ swz) << 4);
            ldsm_x4(qh[0], qh[1], qh[2], qh[3], qaddr);
            ldsm_x4(ql[0], ql[1], ql[2], ql[3], qaddr + 16384);
            uint32_t kchunk = (uint32_t)(((kcc + 2 * c) ^ swz) << 4);
            #pragma unroll
            for (int j = 0; j < 8; j++) {
                uint32_t kh[2], kl[2];
                uint32_t kaddr = kbase + (uint32_t)(j * 1024) + kchunk;
                ldsm_x2(kh[0], kh[1], kaddr);
                ldsm_x2(kl[0], kl[1], kaddr + 8192);
                mma_bf16(s[j], qh, kh);
                mma_bf16(s[j], ql, kh);
                mma_bf16(s[j], qh, kl);
            }
        }

        // ---- masked online softmax ----
        const int clo0 = lo0 - kb, chi0 = hi0 - kb;
        const int clo1 = lo1 - kb, chi1 = hi1 - kb;
        float mt0 = -1e30f, mt1 = -1e30f;
        #pragma unroll
        for (int j = 0; j < 8; j++) {
            int cb = j * 8 + (lane & 3) * 2;
            if (cb >= clo0 && cb < chi0)         mt0 = fmaxf(mt0, s[j][0]);
            if (cb + 1 >= clo0 && cb + 1 < chi0) mt0 = fmaxf(mt0, s[j][1]);
            if (cb >= clo1 && cb < chi1)         mt1 = fmaxf(mt1, s[j][2]);
            if (cb + 1 >= clo1 && cb + 1 < chi1) mt1 = fmaxf(mt1, s[j][3]);
        }
        mt0 = fmaxf(mt0, __shfl_xor_sync(0xffffffffu, mt0, 1));
        mt0 = fmaxf(mt0, __shfl_xor_sync(0xffffffffu, mt0, 2));
        mt1 = fmaxf(mt1, __shfl_xor_sync(0xffffffffu, mt1, 1));
        mt1 = fmaxf(mt1, __shfl_xor_sync(0xffffffffu, mt1, 2));

        float mn0 = fmaxf(m0r, mt0), mn1 = fmaxf(m1r, mt1);
        float a0 = __expf(m0r - mn0), a1 = __expf(m1r - mn1);
        m0r = mn0; m1r = mn1;
        #pragma unroll
        for (int n = 0; n < 8; n++) {
            o[n][0] *= a0; o[n][1] *= a0;
            o[n][2] *= a1; o[n][3] *= a1;
        }

        // ---- fused exp + split + MMA2 ----
        float ps0 = 0.f, ps1 = 0.f;
        #pragma unroll
        for (int c = 0; c < 4; c++) {
            uint32_t pah[4], pal[4];
            #pragma unroll
            for (int jj = 0; jj < 2; jj++) {
                int j = 2 * c + jj;
                int cb = j * 8 + (lane & 3) * 2;
                float p0 = (cb >= clo0 && cb < chi0)         ? __expf(s[j][0] - mn0) : 0.f;
                float p1 = (cb + 1 >= clo0 && cb + 1 < chi0) ? __expf(s[j][1] - mn0) : 0.f;
                float p2 = (cb >= clo1 && cb < chi1)         ? __expf(s[j][2] - mn1) : 0.f;
                float p3 = (cb + 1 >= clo1 && cb + 1 < chi1) ? __expf(s[j][3] - mn1) : 0.f;
                ps0 += p0 + p1; ps1 += p2 + p3;
                split2(p0, p1, pah[2 * jj], pal[2 * jj]);
                split2(p2, p3, pah[2 * jj + 1], pal[2 * jj + 1]);
            }
            uint32_t vcbase = vbase + (uint32_t)(c * 2048);
            #pragma unroll
            for (int n = 0; n < 8; n++) {
                uint32_t vh[2], vl[2];
                uint32_t vaddr = vcbase + (uint32_t)(((n ^ swz)) << 4);
                ldsm_x2t(vh[0], vh[1], vaddr);
                ldsm_x2t(vl[0], vl[1], vaddr + 8192);
                mma_bf16(o[n], pah, vh);
                mma_bf16(o[n], pal, vh);
                mma_bf16(o[n], pah, vl);
            }
        }
        l0r = l0r * a0 + ps0;
        l1r = l1r * a1 + ps1;
        __syncthreads();
    }

    // ---- epilogue ----
    l0r += __shfl_xor_sync(0xffffffffu, l0r, 1);
    l0r += __shfl_xor_sync(0xffffffffu, l0r, 2);
    l1r += __shfl_xor_sync(0xffffffffu, l1r, 1);
    l1r += __shfl_xor_sync(0xffffffffu, l1r, 2);
    float inv0 = l0r > 0.f ? 1.f / l0r : 0.f;
    float inv1 = l1r > 0.f ? 1.f / l1r : 0.f;

    const int t0 = q0 + r0, t1 = t0 + 8;
    const int colb = (lane & 3) * 2;
    if (t0 < T) {
        float* op = out + (size_t)t0 * (HEADS * DIM) + h * DIM + colb;
        #pragma unroll
        for (int n = 0; n < 8; n++)
            *(float2*)(op + n * 8) = make_float2(o[n][0] * inv0, o[n][1] * inv0);
    }
    if (t1 < T) {
        float* op = out + (size_t)t1 * (HEADS * DIM) + h * DIM + colb;
        #pragma unroll
        for (int n = 0; n < 8; n++)
            *(float2*)(op + n * 8) = make_float2(o[n][2] * inv1, o[n][3] * inv1);
    }
}

// ---------------- launch ----------------
extern "C" void kernel_launch(void* const* d_in, const int* in_sizes, int n_in,
                              void* d_out, int out_size)
{
    const float* qkv = (const float*)d_in[0];
    const int*   cu  = (const int*)d_in[1];
    const int T    = in_sizes[0] / (3 * HEADS * DIM);
    const int nseg = in_sizes[1] - 1;

    static bool init = false;
    if (!init) {
        cudaFuncSetAttribute(attn_main, cudaFuncAttributeMaxDynamicSharedMemorySize, SMEM_BYTES);
        init = true;
    }

    prep<<<(T * HEADS * 16 + 255) / 256, 256>>>(qkv, T);
    attn_main<<<dim3((T + BM - 1) / BM, HEADS), NT, SMEM_BYTES>>>(cu, nseg, T, (float*)d_out);
}

// round 6
// speedup vs baseline: 3.7872x; 1.2731x over previous
#include <cuda_runtime.h>
#include <cuda_bf16.h>
#include <cstdint>

#define HEADS 8
#define DIM   64
#define TMAXP 4096
#define BM    128
#define BN    64
#define NT    256

// smem layout (bytes): swizzled 128B rows
#define S_QH 0
#define S_QL 16384
#define S_KV 32768            // + stage*KV_STAGE
#define KV_STAGE 32768
#define T_KH 0
#define T_KL 8192
#define T_VH 16384
#define T_VL 24576
#define S_RS 98304
#define S_RE 98816
#define SMEM_BYTES 99328

#define MASKV -3.0e38f

// ---------------- scratch ----------------
__device__ __align__(16) __nv_bfloat16 g_Qh[(size_t)HEADS * TMAXP * DIM];
__device__ __align__(16) __nv_bfloat16 g_Ql[(size_t)HEADS * TMAXP * DIM];
__device__ __align__(16) __nv_bfloat16 g_Kh[(size_t)HEADS * TMAXP * DIM];
__device__ __align__(16) __nv_bfloat16 g_Kl[(size_t)HEADS * TMAXP * DIM];
__device__ __align__(16) __nv_bfloat16 g_Vh[(size_t)HEADS * TMAXP * DIM];
__device__ __align__(16) __nv_bfloat16 g_Vl[(size_t)HEADS * TMAXP * DIM];

// ---------------- helpers ----------------
__device__ __forceinline__ float ex2(float x) {
    float r;
    asm("ex2.approx.ftz.f32 %0, %1;" : "=f"(r) : "f"(x));
    return r;
}
__device__ __forceinline__ uint32_t smem_u32(const void* p) {
    uint32_t a;
    asm("{ .reg .u64 t; cvta.to.shared.u64 t, %1; cvt.u32.u64 %0, t; }" : "=r"(a) : "l"(p));
    return a;
}
__device__ __forceinline__ void ldsm_x4(uint32_t& r0, uint32_t& r1, uint32_t& r2, uint32_t& r3, uint32_t a) {
    asm volatile("ldmatrix.sync.aligned.m8n8.x4.shared.b16 {%0,%1,%2,%3}, [%4];"
                 : "=r"(r0), "=r"(r1), "=r"(r2), "=r"(r3) : "r"(a));
}
__device__ __forceinline__ void ldsm_x4t(uint32_t& r0, uint32_t& r1, uint32_t& r2, uint32_t& r3, uint32_t a) {
    asm volatile("ldmatrix.sync.aligned.m8n8.x4.trans.shared.b16 {%0,%1,%2,%3}, [%4];"
                 : "=r"(r0), "=r"(r1), "=r"(r2), "=r"(r3) : "r"(a));
}
__device__ __forceinline__ void mma_bf16(float* c, const uint32_t* a, const uint32_t* b) {
    asm volatile("mma.sync.aligned.m16n8k16.row.col.f32.bf16.bf16.f32 "
                 "{%0,%1,%2,%3}, {%4,%5,%6,%7}, {%8,%9}, {%0,%1,%2,%3};"
                 : "+f"(c[0]), "+f"(c[1]), "+f"(c[2]), "+f"(c[3])
                 : "r"(a[0]), "r"(a[1]), "r"(a[2]), "r"(a[3]), "r"(b[0]), "r"(b[1]));
}
__device__ __forceinline__ void split2(float a, float b, uint32_t& hi, uint32_t& lo) {
    uint32_t h;
    asm("cvt.rn.bf16x2.f32 %0, %1, %2;" : "=r"(h) : "f"(b), "f"(a));
    float ah = __uint_as_float(h << 16);
    float bh = __uint_as_float(h & 0xffff0000u);
    uint32_t l;
    float ar = a - ah, br = b - bh;
    asm("cvt.rn.bf16x2.f32 %0, %1, %2;" : "=r"(l) : "f"(br), "f"(ar));
    hi = h; lo = l;
}
#define CP_ASYNC(dst, src, sz) \
    asm volatile("cp.async.cg.shared.global [%0], [%1], 16, %2;" :: "r"(dst), "l"(src), "r"(sz))
#define CP_COMMIT() asm volatile("cp.async.commit_group;" ::: "memory")
#define CP_WAIT0()  asm volatile("cp.async.wait_group 0;" ::: "memory")
#define CP_WAIT1()  asm volatile("cp.async.wait_group 1;" ::: "memory")

// ---------------- prep: fp32 qkv -> bf16 hi/lo, head-major ----------------
__global__ void prep(const float* __restrict__ qkv, int T) {
    int idx = blockIdx.x * blockDim.x + threadIdx.x;
    if (idx >= T * HEADS * 16) return;
    int d4 = idx & 15;
    int h  = (idx >> 4) & (HEADS - 1);
    int t  = idx >> 7;
    const size_t gin = (size_t)t * 1536 + h * 64 + d4 * 4;
    const float4 q = *(const float4*)(qkv + gin);
    const float4 k = *(const float4*)(qkv + gin + 512);
    const float4 v = *(const float4*)(qkv + gin + 1024);
    size_t base = ((size_t)h * TMAXP + t) * DIM + d4 * 4;
    const float s = 0.125f * 1.4426950408889634f;  // 1/sqrt(64) * log2(e)
    uint32_t h0, l0, h1, l1;
    split2(q.x * s, q.y * s, h0, l0); split2(q.z * s, q.w * s, h1, l1);
    *(uint2*)(g_Qh + base) = make_uint2(h0, h1);
    *(uint2*)(g_Ql + base) = make_uint2(l0, l1);
    split2(k.x, k.y, h0, l0); split2(k.z, k.w, h1, l1);
    *(uint2*)(g_Kh + base) = make_uint2(h0, h1);
    *(uint2*)(g_Kl + base) = make_uint2(l0, l1);
    split2(v.x, v.y, h0, l0); split2(v.z, v.w, h1, l1);
    *(uint2*)(g_Vh + base) = make_uint2(h0, h1);
    *(uint2*)(g_Vl + base) = make_uint2(l0, l1);
}

// ---------------- main attention ----------------
__global__ __launch_bounds__(NT, 2)
void attn_main(const int* __restrict__ cu, int nseg, int T, float* __restrict__ out)
{
    extern __shared__ char smem[];
    const uint32_t sb = smem_u32(smem);
    const int tid = threadIdx.x, wid = tid >> 5, lane = tid & 31;
    const int q0 = blockIdx.x * BM;
    const int h  = blockIdx.y;
    int* rs_s = (int*)(smem + S_RS);
    int* re_s = (int*)(smem + S_RE);

    // stage Q tile (hi/lo), swizzled
    {
        const uint4* qh = (const uint4*)(g_Qh + ((size_t)h * TMAXP + q0) * DIM);
        const uint4* ql = (const uint4*)(g_Ql + ((size_t)h * TMAXP + q0) * DIM);
        #pragma unroll
        for (int p = 0; p < 4; p++) {
            int i = tid + p * NT;
            int row = i >> 3, c = i & 7;
            uint32_t soff = (uint32_t)(row * 128 + ((c ^ (row & 7)) << 4));
            if (q0 + row < T) {
                *(uint4*)(smem + S_QH + soff) = qh[i];
                *(uint4*)(smem + S_QL + soff) = ql[i];
            } else {
                const uint4 z = make_uint4(0, 0, 0, 0);
                *(uint4*)(smem + S_QH + soff) = z;
                *(uint4*)(smem + S_QL + soff) = z;
            }
        }
    }
    if (tid < BM) {
        int t = q0 + tid; if (t > T - 1) t = T - 1;
        int s = 0;
        for (int i = 0; i < nseg; i++) if (t >= cu[i]) s = i;
        rs_s[tid] = cu[s]; re_s[tid] = cu[s + 1];
    }
    __syncthreads();
    const int kvlo = rs_s[0];
    const int kvhi = re_s[BM - 1];

    const int m0 = wid * 16;
    const int r0 = m0 + (lane >> 2);
    const int lo0 = rs_s[r0],     hi0 = re_s[r0];
    const int lo1 = rs_s[r0 + 8], hi1 = re_s[r0 + 8];
    const int lomax = lo0 > lo1 ? lo0 : lo1;
    const int himin = hi0 < hi1 ? hi0 : hi1;

    const __nv_bfloat16* gKH = g_Kh + (size_t)h * TMAXP * DIM;
    const __nv_bfloat16* gKL = g_Kl + (size_t)h * TMAXP * DIM;
    const __nv_bfloat16* gVH = g_Vh + (size_t)h * TMAXP * DIM;
    const __nv_bfloat16* gVL = g_Vl + (size_t)h * TMAXP * DIM;

    // cp.async staging geometry
    const int cpc   = tid & 7;
    const int cprow0 = tid >> 3;          // 0..31
    const int cprow1 = cprow0 + 32;       // 32..63
    const uint32_t cpoff0 = (uint32_t)(cprow0 * 128 + ((cpc ^ (cprow0 & 7)) << 4));
    const uint32_t cpoff1 = (uint32_t)(cprow1 * 128 + ((cpc ^ (cprow1 & 7)) << 4));
    const int cpg0 = cprow0 * 64 + cpc * 8;
    const int cpg1 = cprow1 * 64 + cpc * 8;

    float m0r = -1e30f, m1r = -1e30f, l0r = 0.f, l1r = 0.f;
    float o[8][4];
    #pragma unroll
    for (int n = 0; n < 8; n++)
        #pragma unroll
        for (int e = 0; e < 4; e++) o[n][e] = 0.f;

    // fragment address invariants
    const int swz = lane & 7;
    const uint32_t qrow = (uint32_t)((m0 + (lane & 15)) * 128);
    const int qcc = lane >> 4;
    const uint32_t krow4 = (uint32_t)((((lane >> 4) * 8) + (lane & 7)) * 128);
    const int khalf = (lane >> 3) & 1;
    const uint32_t vrow4 = (uint32_t)(((((lane >> 3) & 1) * 8) + (lane & 7)) * 128);
    const int vnsel = lane >> 4;

    const int nIter = (kvhi - kvlo + BN - 1) / BN;

    // prologue: stage tile 0 into buffer 0
    {
        const int kb = kvlo;
        #pragma unroll
        for (int t4 = 0; t4 < 4; t4++) {
            const __nv_bfloat16* g = (t4 == 0) ? gKH : (t4 == 1) ? gKL : (t4 == 2) ? gVH : gVL;
            uint32_t dbase = sb + S_KV + (uint32_t)(t4 * 8192);
            int sz0 = (kb + cprow0 < kvhi) ? 16 : 0;
            int sz1 = (kb + cprow1 < kvhi) ? 16 : 0;
            CP_ASYNC(dbase + cpoff0, g + (size_t)kb * DIM + cpg0, sz0);
            CP_ASYNC(dbase + cpoff1, g + (size_t)kb * DIM + cpg1, sz1);
        }
        CP_COMMIT();
    }

    for (int it = 0; it < nIter; it++) {
        const int kb = kvlo + it * BN;
        if (it + 1 < nIter) {
            const int kn = kb + BN;
            uint32_t nbase = sb + S_KV + (uint32_t)(((it + 1) & 1) * KV_STAGE);
            #pragma unroll
            for (int t4 = 0; t4 < 4; t4++) {
                const __nv_bfloat16* g = (t4 == 0) ? gKH : (t4 == 1) ? gKL : (t4 == 2) ? gVH : gVL;
                uint32_t dbase = nbase + (uint32_t)(t4 * 8192);
                int sz0 = (kn + cprow0 < kvhi) ? 16 : 0;
                int sz1 = (kn + cprow1 < kvhi) ? 16 : 0;
                CP_ASYNC(dbase + cpoff0, g + (size_t)kn * DIM + cpg0, sz0);
                CP_ASYNC(dbase + cpoff1, g + (size_t)kn * DIM + cpg1, sz1);
            }
            CP_COMMIT();
            CP_WAIT1();
        } else {
            CP_WAIT0();
        }
        __syncthreads();

        const uint32_t kvb = sb + S_KV + (uint32_t)((it & 1) * KV_STAGE);
        const uint32_t kbase = kvb + T_KH + krow4;
        const uint32_t vbase = kvb + T_VH + vrow4;

        // ---- MMA1: S = Qh Kh^T + Ql Kh^T + Qh Kl^T ----
        float s[8][4];
        #pragma unroll
        for (int n = 0; n < 8; n++)
            #pragma unroll
            for (int e = 0; e < 4; e++) s[n][e] = 0.f;

        #pragma unroll
        for (int c = 0; c < 4; c++) {
            uint32_t qh[4], ql[4];
            uint32_t qaddr = sb + S_QH + qrow + (uint32_t)(((qcc + 2 * c) ^ swz) << 4);
            ldsm_x4(qh[0], qh[1], qh[2], qh[3], qaddr);
            ldsm_x4(ql[0], ql[1], ql[2], ql[3], qaddr + 16384);
            const uint32_t kchunk = (uint32_t)(((khalf + 2 * c) ^ swz) << 4);
            #pragma unroll
            for (int jp = 0; jp < 4; jp++) {
                uint32_t kh[4], kl[4];
                uint32_t kaddr = kbase + (uint32_t)(jp * 2048) + kchunk;
                ldsm_x4(kh[0], kh[1], kh[2], kh[3], kaddr);
                ldsm_x4(kl[0], kl[1], kl[2], kl[3], kaddr + 8192);
                mma_bf16(s[2 * jp],     qh, kh);
                mma_bf16(s[2 * jp],     ql, kh);
                mma_bf16(s[2 * jp],     qh, kl);
                mma_bf16(s[2 * jp + 1], qh, kh + 2);
                mma_bf16(s[2 * jp + 1], ql, kh + 2);
                mma_bf16(s[2 * jp + 1], qh, kl + 2);
            }
        }

        // ---- boundary tiles only: clamp invalid entries ----
        if (kb < lomax || kb + BN > himin) {
            const int clo0 = lo0 - kb, chi0 = hi0 - kb;
            const int clo1 = lo1 - kb, chi1 = hi1 - kb;
            #pragma unroll
            for (int j = 0; j < 8; j++) {
                int cb = j * 8 + (lane & 3) * 2;
                if (cb < clo0     || cb >= chi0)     s[j][0] = MASKV;
                if (cb + 1 < clo0 || cb + 1 >= chi0) s[j][1] = MASKV;
                if (cb < clo1     || cb >= chi1)     s[j][2] = MASKV;
                if (cb + 1 < clo1 || cb + 1 >= chi1) s[j][3] = MASKV;
            }
        }

        // ---- online softmax (unconditional) ----
        float mt0 = -1e30f, mt1 = -1e30f;
        #pragma unroll
        for (int j = 0; j < 8; j++) {
            mt0 = fmaxf(mt0, fmaxf(s[j][0], s[j][1]));
            mt1 = fmaxf(mt1, fmaxf(s[j][2], s[j][3]));
        }
        mt0 = fmaxf(mt0, __shfl_xor_sync(0xffffffffu, mt0, 1));
        mt0 = fmaxf(mt0, __shfl_xor_sync(0xffffffffu, mt0, 2));
        mt1 = fmaxf(mt1, __shfl_xor_sync(0xffffffffu, mt1, 1));
        mt1 = fmaxf(mt1, __shfl_xor_sync(0xffffffffu, mt1, 2));

        float mn0 = fmaxf(m0r, mt0), mn1 = fmaxf(m1r, mt1);
        float a0 = ex2(m0r - mn0), a1 = ex2(m1r - mn1);
        m0r = mn0; m1r = mn1;
        #pragma unroll
        for (int n = 0; n < 8; n++) {
            o[n][0] *= a0; o[n][1] *= a0;
            o[n][2] *= a1; o[n][3] *= a1;
        }

        // ---- fused exp2 + split + MMA2 ----
        float ps0 = 0.f, ps1 = 0.f;
        #pragma unroll
        for (int c = 0; c < 4; c++) {
            uint32_t pah[4], pal[4];
            #pragma unroll
            for (int jj = 0; jj < 2; jj++) {
                int j = 2 * c + jj;
                float p0 = ex2(s[j][0] - mn0);
                float p1 = ex2(s[j][1] - mn0);
                float p2 = ex2(s[j][2] - mn1);
                float p3 = ex2(s[j][3] - mn1);
                ps0 += p0 + p1; ps1 += p2 + p3;
                split2(p0, p1, pah[2 * jj], pal[2 * jj]);
                split2(p2, p3, pah[2 * jj + 1], pal[2 * jj + 1]);
            }
            uint32_t vcbase = vbase + (uint32_t)(c * 2048);
            #pragma unroll
            for (int np = 0; np < 4; np++) {
                uint32_t vh[4], vl[4];
                uint32_t vaddr = vcbase + (uint32_t)(((2 * np + vnsel) ^ swz) << 4);
                ldsm_x4t(vh[0], vh[1], vh[2], vh[3], vaddr);
                ldsm_x4t(vl[0], vl[1], vl[2], vl[3], vaddr + 8192);
                mma_bf16(o[2 * np],     pah, vh);
                mma_bf16(o[2 * np],     pal, vh);
                mma_bf16(o[2 * np],     pah, vl);
                mma_bf16(o[2 * np + 1], pah, vh + 2);
                mma_bf16(o[2 * np + 1], pal, vh + 2);
                mma_bf16(o[2 * np + 1], pah, vl + 2);
            }
        }
        l0r = l0r * a0 + ps0;
        l1r = l1r * a1 + ps1;
        __syncthreads();
    }

    // ---- epilogue ----
    l0r += __shfl_xor_sync(0xffffffffu, l0r, 1);
    l0r += __shfl_xor_sync(0xffffffffu, l0r, 2);
    l1r += __shfl_xor_sync(0xffffffffu, l1r, 1);
    l1r += __shfl_xor_sync(0xffffffffu, l1r, 2);
    float inv0 = l0r > 0.f ? 1.f / l0r : 0.f;
    float inv1 = l1r > 0.f ? 1.f / l1r : 0.f;

    const int t0 = q0 + r0, t1 = t0 + 8;
    const int colb = (lane & 3) * 2;
    if (t0 < T) {
        float* op = out + (size_t)t0 * (HEADS * DIM) + h * DIM + colb;
        #pragma unroll
        for (int n = 0; n < 8; n++)
            *(float2*)(op + n * 8) = make_float2(o[n][0] * inv0, o[n][1] * inv0);
    }
    if (t1 < T) {
        float* op = out + (size_t)t1 * (HEADS * DIM) + h * DIM + colb;
        #pragma unroll
        for (int n = 0; n < 8; n++)
            *(float2*)(op + n * 8) = make_float2(o[n][2] * inv1, o[n][3] * inv1);
    }
}

// ---------------- launch ----------------
extern "C" void kernel_launch(void* const* d_in, const int* in_sizes, int n_in,
                              void* d_out, int out_size)
{
    const float* qkv = (const float*)d_in[0];
    const int*   cu  = (const int*)d_in[1];
    const int T    = in_sizes[0] / (3 * HEADS * DIM);
    const int nseg = in_sizes[1] - 1;

    static bool init = false;
    if (!init) {
        cudaFuncSetAttribute(attn_main, cudaFuncAttributeMaxDynamicSharedMemorySize, SMEM_BYTES);
        init = true;
    }

    prep<<<(T * HEADS * 16 + 255) / 256, 256>>>(qkv, T);
    attn_main<<<dim3((T + BM - 1) / BM, HEADS), NT, SMEM_BYTES>>>(cu, nseg, T, (float*)d_out);
}

// round 7
// speedup vs baseline: 5.2753x; 1.3929x over previous
#include <cuda_runtime.h>
#include <cuda_fp16.h>
#include <cstdint>

#define HEADS 8
#define DIM   64
#define TMAXP 4096
#define BM    128
#define BN    64
#define NT    256

// smem layout (bytes): swizzled 128B rows
#define S_QH 0
#define S_QL 16384
#define S_KV 32768            // + stage*KV_STAGE
#define KV_STAGE 24576
#define T_KH 0
#define T_VH 8192
#define T_VL 16384
#define S_RS 81920
#define S_RE 82432
#define SMEM_BYTES 82944

#define MASKV -3.0e38f

// ---------------- scratch (fp16) ----------------
__device__ __align__(16) __half g_Qh[(size_t)HEADS * TMAXP * DIM];
__device__ __align__(16) __half g_Ql[(size_t)HEADS * TMAXP * DIM];
__device__ __align__(16) __half g_Kh[(size_t)HEADS * TMAXP * DIM];
__device__ __align__(16) __half g_Vh[(size_t)HEADS * TMAXP * DIM];
__device__ __align__(16) __half g_Vl[(size_t)HEADS * TMAXP * DIM];

// ---------------- helpers ----------------
__device__ __forceinline__ float ex2(float x) {
    float r;
    asm("ex2.approx.ftz.f32 %0, %1;" : "=f"(r) : "f"(x));
    return r;
}
__device__ __forceinline__ uint32_t smem_u32(const void* p) {
    uint32_t a;
    asm("{ .reg .u64 t; cvta.to.shared.u64 t, %1; cvt.u32.u64 %0, t; }" : "=r"(a) : "l"(p));
    return a;
}
__device__ __forceinline__ void ldsm_x4(uint32_t& r0, uint32_t& r1, uint32_t& r2, uint32_t& r3, uint32_t a) {
    asm volatile("ldmatrix.sync.aligned.m8n8.x4.shared.b16 {%0,%1,%2,%3}, [%4];"
                 : "=r"(r0), "=r"(r1), "=r"(r2), "=r"(r3) : "r"(a));
}
__device__ __forceinline__ void ldsm_x4t(uint32_t& r0, uint32_t& r1, uint32_t& r2, uint32_t& r3, uint32_t a) {
    asm volatile("ldmatrix.sync.aligned.m8n8.x4.trans.shared.b16 {%0,%1,%2,%3}, [%4];"
                 : "=r"(r0), "=r"(r1), "=r"(r2), "=r"(r3) : "r"(a));
}
__device__ __forceinline__ void mma_f16(float* c, const uint32_t* a, const uint32_t* b) {
    asm volatile("mma.sync.aligned.m16n8k16.row.col.f32.f16.f16.f32 "
                 "{%0,%1,%2,%3}, {%4,%5,%6,%7}, {%8,%9}, {%0,%1,%2,%3};"
                 : "+f"(c[0]), "+f"(c[1]), "+f"(c[2]), "+f"(c[3])
                 : "r"(a[0]), "r"(a[1]), "r"(a[2]), "r"(a[3]), "r"(b[0]), "r"(b[1]));
}
// pack two floats to fp16x2 (lo = a, hi = b)
__device__ __forceinline__ uint32_t packh2(float a, float b) {
    uint32_t r;
    asm("cvt.rn.f16x2.f32 %0, %1, %2;" : "=r"(r) : "f"(b), "f"(a));
    return r;
}
// split pair of floats into packed fp16 hi + packed fp16 residual
__device__ __forceinline__ void split2h(float a, float b, uint32_t& hi, uint32_t& lo) {
    uint32_t h = packh2(a, b);
    __half2 hv = *(__half2*)&h;
    float2 back = __half22float2(hv);
    lo = packh2(a - back.x, b - back.y);
    hi = h;
}
#define CP_ASYNC(dst, src, sz) \
    asm volatile("cp.async.cg.shared.global [%0], [%1], 16, %2;" :: "r"(dst), "l"(src), "r"(sz))
#define CP_COMMIT() asm volatile("cp.async.commit_group;" ::: "memory")
#define CP_WAIT0()  asm volatile("cp.async.wait_group 0;" ::: "memory")
#define CP_WAIT1()  asm volatile("cp.async.wait_group 1;" ::: "memory")

// ---------------- prep: fp32 qkv -> fp16 (Q hi/lo, K hi, V hi/lo) ----------------
__global__ void prep(const float* __restrict__ qkv, int T) {
    int idx = blockIdx.x * blockDim.x + threadIdx.x;
    if (idx >= T * HEADS * 16) return;
    int d4 = idx & 15;
    int h  = (idx >> 4) & (HEADS - 1);
    int t  = idx >> 7;
    const size_t gin = (size_t)t * 1536 + h * 64 + d4 * 4;
    const float4 q = *(const float4*)(qkv + gin);
    const float4 k = *(const float4*)(qkv + gin + 512);
    const float4 v = *(const float4*)(qkv + gin + 1024);
    size_t base = ((size_t)h * TMAXP + t) * DIM + d4 * 4;
    const float s = 0.125f * 1.4426950408889634f;  // 1/sqrt(64) * log2(e)
    uint32_t h0, l0, h1, l1;
    split2h(q.x * s, q.y * s, h0, l0); split2h(q.z * s, q.w * s, h1, l1);
    *(uint2*)(g_Qh + base) = make_uint2(h0, h1);
    *(uint2*)(g_Ql + base) = make_uint2(l0, l1);
    *(uint2*)(g_Kh + base) = make_uint2(packh2(k.x, k.y), packh2(k.z, k.w));
    split2h(v.x, v.y, h0, l0); split2h(v.z, v.w, h1, l1);
    *(uint2*)(g_Vh + base) = make_uint2(h0, h1);
    *(uint2*)(g_Vl + base) = make_uint2(l0, l1);
}

// ---------------- main attention ----------------
__global__ __launch_bounds__(NT, 2)
void attn_main(const int* __restrict__ cu, int nseg, int T, float* __restrict__ out)
{
    extern __shared__ char smem[];
    const uint32_t sb = smem_u32(smem);
    const int tid = threadIdx.x, wid = tid >> 5, lane = tid & 31;
    const int q0 = blockIdx.x * BM;
    const int h  = blockIdx.y;
    int* rs_s = (int*)(smem + S_RS);
    int* re_s = (int*)(smem + S_RE);

    // stage Q tile (hi/lo), swizzled
    {
        const uint4* qh = (const uint4*)(g_Qh + ((size_t)h * TMAXP + q0) * DIM);
        const uint4* ql = (const uint4*)(g_Ql + ((size_t)h * TMAXP + q0) * DIM);
        #pragma unroll
        for (int p = 0; p < 4; p++) {
            int i = tid + p * NT;
            int row = i >> 3, c = i & 7;
            uint32_t soff = (uint32_t)(row * 128 + ((c ^ (row & 7)) << 4));
            if (q0 + row < T) {
                *(uint4*)(smem + S_QH + soff) = qh[i];
                *(uint4*)(smem + S_QL + soff) = ql[i];
            } else {
                const uint4 z = make_uint4(0, 0, 0, 0);
                *(uint4*)(smem + S_QH + soff) = z;
                *(uint4*)(smem + S_QL + soff) = z;
            }
        }
    }
    if (tid < BM) {
        int t = q0 + tid; if (t > T - 1) t = T - 1;
        int s = 0;
        for (int i = 0; i < nseg; i++) if (t >= cu[i]) s = i;
        rs_s[tid] = cu[s]; re_s[tid] = cu[s + 1];
    }
    __syncthreads();
    const int kvlo = rs_s[0];
    const int kvhi = re_s[BM - 1];

    const int m0 = wid * 16;
    const int r0 = m0 + (lane >> 2);
    const int lo0 = rs_s[r0],     hi0 = re_s[r0];
    const int lo1 = rs_s[r0 + 8], hi1 = re_s[r0 + 8];
    const int lomax = lo0 > lo1 ? lo0 : lo1;
    const int himin = hi0 < hi1 ? hi0 : hi1;

    const __half* gKH = g_Kh + (size_t)h * TMAXP * DIM;
    const __half* gVH = g_Vh + (size_t)h * TMAXP * DIM;
    const __half* gVL = g_Vl + (size_t)h * TMAXP * DIM;

    // cp.async staging geometry
    const int cpc   = tid & 7;
    const int cprow0 = tid >> 3;          // 0..31
    const int cprow1 = cprow0 + 32;       // 32..63
    const uint32_t cpoff0 = (uint32_t)(cprow0 * 128 + ((cpc ^ (cprow0 & 7)) << 4));
    const uint32_t cpoff1 = (uint32_t)(cprow1 * 128 + ((cpc ^ (cprow1 & 7)) << 4));
    const int cpg0 = cprow0 * 64 + cpc * 8;
    const int cpg1 = cprow1 * 64 + cpc * 8;

    float m0r = -1e30f, m1r = -1e30f, l0r = 0.f, l1r = 0.f;
    float o[8][4];
    #pragma unroll
    for (int n = 0; n < 8; n++)
        #pragma unroll
        for (int e = 0; e < 4; e++) o[n][e] = 0.f;

    // fragment address invariants
    const int swz = lane & 7;
    const uint32_t qrow = (uint32_t)((m0 + (lane & 15)) * 128);
    const int qcc = lane >> 4;
    const uint32_t krow4 = (uint32_t)((((lane >> 4) * 8) + (lane & 7)) * 128);
    const int khalf = (lane >> 3) & 1;
    const uint32_t vrow4 = (uint32_t)(((((lane >> 3) & 1) * 8) + (lane & 7)) * 128);
    const int vnsel = lane >> 4;

    const int nIter = (kvhi - kvlo + BN - 1) / BN;

    // prologue: stage tile 0 into buffer 0
    {
        const int kb = kvlo;
        #pragma unroll
        for (int t3 = 0; t3 < 3; t3++) {
            const __half* g = (t3 == 0) ? gKH : (t3 == 1) ? gVH : gVL;
            uint32_t dbase = sb + S_KV + (uint32_t)(t3 * 8192);
            int sz0 = (kb + cprow0 < kvhi) ? 16 : 0;
            int sz1 = (kb + cprow1 < kvhi) ? 16 : 0;
            CP_ASYNC(dbase + cpoff0, g + (size_t)kb * DIM + cpg0, sz0);
            CP_ASYNC(dbase + cpoff1, g + (size_t)kb * DIM + cpg1, sz1);
        }
        CP_COMMIT();
    }

    for (int it = 0; it < nIter; it++) {
        const int kb = kvlo + it * BN;
        if (it + 1 < nIter) {
            const int kn = kb + BN;
            uint32_t nbase = sb + S_KV + (uint32_t)(((it + 1) & 1) * KV_STAGE);
            #pragma unroll
            for (int t3 = 0; t3 < 3; t3++) {
                const __half* g = (t3 == 0) ? gKH : (t3 == 1) ? gVH : gVL;
                uint32_t dbase = nbase + (uint32_t)(t3 * 8192);
                int sz0 = (kn + cprow0 < kvhi) ? 16 : 0;
                int sz1 = (kn + cprow1 < kvhi) ? 16 : 0;
                CP_ASYNC(dbase + cpoff0, g + (size_t)kn * DIM + cpg0, sz0);
                CP_ASYNC(dbase + cpoff1, g + (size_t)kn * DIM + cpg1, sz1);
            }
            CP_COMMIT();
            CP_WAIT1();
        } else {
            CP_WAIT0();
        }
        __syncthreads();

        const uint32_t kvb = sb + S_KV + (uint32_t)((it & 1) * KV_STAGE);
        const uint32_t kbase = kvb + T_KH + krow4;
        const uint32_t vbase = kvb + T_VH + vrow4;

        // ---- MMA1: S = Qh Kh^T + Ql Kh^T ----
        float s[8][4];
        #pragma unroll
        for (int n = 0; n < 8; n++)
            #pragma unroll
            for (int e = 0; e < 4; e++) s[n][e] = 0.f;

        #pragma unroll
        for (int c = 0; c < 4; c++) {
            uint32_t qh[4], ql[4];
            uint32_t qaddr = sb + S_QH + qrow + (uint32_t)(((qcc + 2 * c) ^ swz) << 4);
            ldsm_x4(qh[0], qh[1], qh[2], qh[3], qaddr);
            ldsm_x4(ql[0], ql[1], ql[2], ql[3], qaddr + 16384);
            const uint32_t kchunk = (uint32_t)(((khalf + 2 * c) ^ swz) << 4);
            #pragma unroll
            for (int jp = 0; jp < 4; jp++) {
                uint32_t kh[4];
                uint32_t kaddr = kbase + (uint32_t)(jp * 2048) + kchunk;
                ldsm_x4(kh[0], kh[1], kh[2], kh[3], kaddr);
                mma_f16(s[2 * jp],     qh, kh);
                mma_f16(s[2 * jp],     ql, kh);
                mma_f16(s[2 * jp + 1], qh, kh + 2);
                mma_f16(s[2 * jp + 1], ql, kh + 2);
            }
        }

        // ---- boundary tiles only: clamp invalid entries ----
        if (kb < lomax || kb + BN > himin) {
            const int clo0 = lo0 - kb, chi0 = hi0 - kb;
            const int clo1 = lo1 - kb, chi1 = hi1 - kb;
            #pragma unroll
            for (int j = 0; j < 8; j++) {
                int cb = j * 8 + (lane & 3) * 2;
                if (cb < clo0     || cb >= chi0)     s[j][0] = MASKV;
                if (cb + 1 < clo0 || cb + 1 >= chi0) s[j][1] = MASKV;
                if (cb < clo1     || cb >= chi1)     s[j][2] = MASKV;
                if (cb + 1 < clo1 || cb + 1 >= chi1) s[j][3] = MASKV;
            }
        }

        // ---- online softmax (unconditional) ----
        float mt0 = -1e30f, mt1 = -1e30f;
        #pragma unroll
        for (int j = 0; j < 8; j++) {
            mt0 = fmaxf(mt0, fmaxf(s[j][0], s[j][1]));
            mt1 = fmaxf(mt1, fmaxf(s[j][2], s[j][3]));
        }
        mt0 = fmaxf(mt0, __shfl_xor_sync(0xffffffffu, mt0, 1));
        mt0 = fmaxf(mt0, __shfl_xor_sync(0xffffffffu, mt0, 2));
        mt1 = fmaxf(mt1, __shfl_xor_sync(0xffffffffu, mt1, 1));
        mt1 = fmaxf(mt1, __shfl_xor_sync(0xffffffffu, mt1, 2));

        float mn0 = fmaxf(m0r, mt0), mn1 = fmaxf(m1r, mt1);
        float a0 = ex2(m0r - mn0), a1 = ex2(m1r - mn1);
        m0r = mn0; m1r = mn1;
        #pragma unroll
        for (int n = 0; n < 8; n++) {
            o[n][0] *= a0; o[n][1] *= a0;
            o[n][2] *= a1; o[n][3] *= a1;
        }

        // ---- fused exp2 + pack + MMA2: O += P Vh + P Vl ----
        float ps0 = 0.f, ps1 = 0.f;
        #pragma unroll
        for (int c = 0; c < 4; c++) {
            uint32_t pa[4];
            #pragma unroll
            for (int jj = 0; jj < 2; jj++) {
                int j = 2 * c + jj;
                float p0 = ex2(s[j][0] - mn0);
                float p1 = ex2(s[j][1] - mn0);
                float p2 = ex2(s[j][2] - mn1);
                float p3 = ex2(s[j][3] - mn1);
                ps0 += p0 + p1; ps1 += p2 + p3;
                pa[2 * jj]     = packh2(p0, p1);
                pa[2 * jj + 1] = packh2(p2, p3);
            }
            uint32_t vcbase = vbase + (uint32_t)(c * 2048);
            #pragma unroll
            for (int np = 0; np < 4; np++) {
                uint32_t vh[4], vl[4];
                uint32_t vaddr = vcbase + (uint32_t)(((2 * np + vnsel) ^ swz) << 4);
                ldsm_x4t(vh[0], vh[1], vh[2], vh[3], vaddr);
                ldsm_x4t(vl[0], vl[1], vl[2], vl[3], vaddr + 8192);
                mma_f16(o[2 * np],     pa, vh);
                mma_f16(o[2 * np],     pa, vl);
                mma_f16(o[2 * np + 1], pa, vh + 2);
                mma_f16(o[2 * np + 1], pa, vl + 2);
            }
        }
        l0r = l0r * a0 + ps0;
        l1r = l1r * a1 + ps1;
        __syncthreads();
    }

    // ---- epilogue ----
    l0r += __shfl_xor_sync(0xffffffffu, l0r, 1);
    l0r += __shfl_xor_sync(0xffffffffu, l0r, 2);
    l1r += __shfl_xor_sync(0xffffffffu, l1r, 1);
    l1r += __shfl_xor_sync(0xffffffffu, l1r, 2);
    float inv0 = l0r > 0.f ? 1.f / l0r : 0.f;
    float inv1 = l1r > 0.f ? 1.f / l1r : 0.f;

    const int t0 = q0 + r0, t1 = t0 + 8;
    const int colb = (lane & 3) * 2;
    if (t0 < T) {
        float* op = out + (size_t)t0 * (HEADS * DIM) + h * DIM + colb;
        #pragma unroll
        for (int n = 0; n < 8; n++)
            *(float2*)(op + n * 8) = make_float2(o[n][0] * inv0, o[n][1] * inv0);
    }
    if (t1 < T) {
        float* op = out + (size_t)t1 * (HEADS * DIM) + h * DIM + colb;
        #pragma unroll
        for (int n = 0; n < 8; n++)
            *(float2*)(op + n * 8) = make_float2(o[n][2] * inv1, o[n][3] * inv1);
    }
}

// ---------------- launch ----------------
extern "C" void kernel_launch(void* const* d_in, const int* in_sizes, int n_in,
                              void* d_out, int out_size)
{
    const float* qkv = (const float*)d_in[0];
    const int*   cu  = (const int*)d_in[1];
    const int T    = in_sizes[0] / (3 * HEADS * DIM);
    const int nseg = in_sizes[1] - 1;

    static bool init = false;
    if (!init) {
        cudaFuncSetAttribute(attn_main, cudaFuncAttributeMaxDynamicSharedMemorySize, SMEM_BYTES);
        init = true;
    }

    prep<<<(T * HEADS * 16 + 255) / 256, 256>>>(qkv, T);
    attn_main<<<dim3((T + BM - 1) / BM, HEADS), NT, SMEM_BYTES>>>(cu, nseg, T, (float*)d_out);
}

// round 8
// speedup vs baseline: 6.2666x; 1.1879x over previous
#include <cuda_runtime.h>
#include <cuda_fp16.h>
#include <cstdint>

#define HEADS 8
#define DIM   64
#define TMAXP 4096
#define BM    128
#define BN    64
#define NT    256

// smem layout (bytes): swizzled 128B rows
#define S_QH 0
#define S_QL 16384
#define S_KV 32768            // + stage*KV_STAGE
#define KV_STAGE 16384
#define T_KH 0
#define T_VH 8192
#define S_RS 65536
#define S_RE 66048
#define SMEM_BYTES 66560

#define MASKV -3.0e38f

// ---------------- scratch (fp16) ----------------
__device__ __align__(16) __half g_Qh[(size_t)HEADS * TMAXP * DIM];
__device__ __align__(16) __half g_Ql[(size_t)HEADS * TMAXP * DIM];
__device__ __align__(16) __half g_Kh[(size_t)HEADS * TMAXP * DIM];
__device__ __align__(16) __half g_Vh[(size_t)HEADS * TMAXP * DIM];

// ---------------- helpers ----------------
__device__ __forceinline__ float ex2(float x) {
    float r;
    asm("ex2.approx.ftz.f32 %0, %1;" : "=f"(r) : "f"(x));
    return r;
}
__device__ __forceinline__ uint32_t smem_u32(const void* p) {
    uint32_t a;
    asm("{ .reg .u64 t; cvta.to.shared.u64 t, %1; cvt.u32.u64 %0, t; }" : "=r"(a) : "l"(p));
    return a;
}
__device__ __forceinline__ void ldsm_x4(uint32_t& r0, uint32_t& r1, uint32_t& r2, uint32_t& r3, uint32_t a) {
    asm volatile("ldmatrix.sync.aligned.m8n8.x4.shared.b16 {%0,%1,%2,%3}, [%4];"
                 : "=r"(r0), "=r"(r1), "=r"(r2), "=r"(r3) : "r"(a));
}
__device__ __forceinline__ void ldsm_x4t(uint32_t& r0, uint32_t& r1, uint32_t& r2, uint32_t& r3, uint32_t a) {
    asm volatile("ldmatrix.sync.aligned.m8n8.x4.trans.shared.b16 {%0,%1,%2,%3}, [%4];"
                 : "=r"(r0), "=r"(r1), "=r"(r2), "=r"(r3) : "r"(a));
}
__device__ __forceinline__ void mma_f16(float* c, const uint32_t* a, const uint32_t* b) {
    asm volatile("mma.sync.aligned.m16n8k16.row.col.f32.f16.f16.f32 "
                 "{%0,%1,%2,%3}, {%4,%5,%6,%7}, {%8,%9}, {%0,%1,%2,%3};"
                 : "+f"(c[0]), "+f"(c[1]), "+f"(c[2]), "+f"(c[3])
                 : "r"(a[0]), "r"(a[1]), "r"(a[2]), "r"(a[3]), "r"(b[0]), "r"(b[1]));
}
// pack two floats to fp16x2 (lo = a, hi = b)
__device__ __forceinline__ uint32_t packh2(float a, float b) {
    uint32_t r;
    asm("cvt.rn.f16x2.f32 %0, %1, %2;" : "=r"(r) : "f"(b), "f"(a));
    return r;
}
// split pair of floats into packed fp16 hi + packed fp16 residual
__device__ __forceinline__ void split2h(float a, float b, uint32_t& hi, uint32_t& lo) {
    uint32_t h = packh2(a, b);
    __half2 hv = *(__half2*)&h;
    float2 back = __half22float2(hv);
    lo = packh2(a - back.x, b - back.y);
    hi = h;
}
#define CP_ASYNC(dst, src, sz) \
    asm volatile("cp.async.cg.shared.global [%0], [%1], 16, %2;" :: "r"(dst), "l"(src), "r"(sz))
#define CP_COMMIT() asm volatile("cp.async.commit_group;" ::: "memory")
#define CP_WAIT0()  asm volatile("cp.async.wait_group 0;" ::: "memory")
#define CP_WAIT1()  asm volatile("cp.async.wait_group 1;" ::: "memory")

// ---------------- prep: fp32 qkv -> fp16 (Q hi/lo, K hi, V hi) ----------------
__global__ void prep(const float* __restrict__ qkv, int T) {
    int idx = blockIdx.x * blockDim.x + threadIdx.x;
    if (idx >= T * HEADS * 16) return;
    int d4 = idx & 15;
    int h  = (idx >> 4) & (HEADS - 1);
    int t  = idx >> 7;
    const size_t gin = (size_t)t * 1536 + h * 64 + d4 * 4;
    const float4 q = *(const float4*)(qkv + gin);
    const float4 k = *(const float4*)(qkv + gin + 512);
    const float4 v = *(const float4*)(qkv + gin + 1024);
    size_t base = ((size_t)h * TMAXP + t) * DIM + d4 * 4;
    const float s = 0.125f * 1.4426950408889634f;  // 1/sqrt(64) * log2(e)
    uint32_t h0, l0, h1, l1;
    split2h(q.x * s, q.y * s, h0, l0); split2h(q.z * s, q.w * s, h1, l1);
    *(uint2*)(g_Qh + base) = make_uint2(h0, h1);
    *(uint2*)(g_Ql + base) = make_uint2(l0, l1);
    *(uint2*)(g_Kh + base) = make_uint2(packh2(k.x, k.y), packh2(k.z, k.w));
    *(uint2*)(g_Vh + base) = make_uint2(packh2(v.x, v.y), packh2(v.z, v.w));
}

// ---------------- main attention ----------------
__global__ __launch_bounds__(NT, 2)
void attn_main(const int* __restrict__ cu, int nseg, int T, float* __restrict__ out)
{
    extern __shared__ char smem[];
    const uint32_t sb = smem_u32(smem);
    const int tid = threadIdx.x, wid = tid >> 5, lane = tid & 31;
    const int q0 = blockIdx.x * BM;
    const int h  = blockIdx.y;
    int* rs_s = (int*)(smem + S_RS);
    int* re_s = (int*)(smem + S_RE);

    // stage Q tile (hi/lo), swizzled
    {
        const uint4* qh = (const uint4*)(g_Qh + ((size_t)h * TMAXP + q0) * DIM);
        const uint4* ql = (const uint4*)(g_Ql + ((size_t)h * TMAXP + q0) * DIM);
        #pragma unroll
        for (int p = 0; p < 4; p++) {
            int i = tid + p * NT;
            int row = i >> 3, c = i & 7;
            uint32_t soff = (uint32_t)(row * 128 + ((c ^ (row & 7)) << 4));
            if (q0 + row < T) {
                *(uint4*)(smem + S_QH + soff) = qh[i];
                *(uint4*)(smem + S_QL + soff) = ql[i];
            } else {
                const uint4 z = make_uint4(0, 0, 0, 0);
                *(uint4*)(smem + S_QH + soff) = z;
                *(uint4*)(smem + S_QL + soff) = z;
            }
        }
    }
    if (tid < BM) {
        int t = q0 + tid; if (t > T - 1) t = T - 1;
        int s = 0;
        for (int i = 0; i < nseg; i++) if (t >= cu[i]) s = i;
        rs_s[tid] = cu[s]; re_s[tid] = cu[s + 1];
    }
    __syncthreads();
    const int kvlo = rs_s[0];
    const int kvhi = re_s[BM - 1];

    const int m0 = wid * 16;
    const int r0 = m0 + (lane >> 2);
    const int lo0 = rs_s[r0],     hi0 = re_s[r0];
    const int lo1 = rs_s[r0 + 8], hi1 = re_s[r0 + 8];
    const int lomax = lo0 > lo1 ? lo0 : lo1;
    const int himin = hi0 < hi1 ? hi0 : hi1;

    const __half* gKH = g_Kh + (size_t)h * TMAXP * DIM;
    const __half* gVH = g_Vh + (size_t)h * TMAXP * DIM;

    // cp.async staging geometry
    const int cpc   = tid & 7;
    const int cprow0 = tid >> 3;          // 0..31
    const int cprow1 = cprow0 + 32;       // 32..63
    const uint32_t cpoff0 = (uint32_t)(cprow0 * 128 + ((cpc ^ (cprow0 & 7)) << 4));
    const uint32_t cpoff1 = (uint32_t)(cprow1 * 128 + ((cpc ^ (cprow1 & 7)) << 4));
    const int cpg0 = cprow0 * 64 + cpc * 8;
    const int cpg1 = cprow1 * 64 + cpc * 8;

    float m0r = -1e30f, m1r = -1e30f, l0r = 0.f, l1r = 0.f;
    float o[8][4];
    #pragma unroll
    for (int n = 0; n < 8; n++)
        #pragma unroll
        for (int e = 0; e < 4; e++) o[n][e] = 0.f;

    // fragment address invariants
    const int swz = lane & 7;
    const uint32_t qrow = (uint32_t)((m0 + (lane & 15)) * 128);
    const int qcc = lane >> 4;
    const uint32_t krow4 = (uint32_t)((((lane >> 4) * 8) + (lane & 7)) * 128);
    const int khalf = (lane >> 3) & 1;
    const uint32_t vrow4 = (uint32_t)(((((lane >> 3) & 1) * 8) + (lane & 7)) * 128);
    const int vnsel = lane >> 4;

    const int nIter = (kvhi - kvlo + BN - 1) / BN;

    // prologue: stage tile 0 into buffer 0
    {
        const int kb = kvlo;
        #pragma unroll
        for (int t2 = 0; t2 < 2; t2++) {
            const __half* g = (t2 == 0) ? gKH : gVH;
            uint32_t dbase = sb + S_KV + (uint32_t)(t2 * 8192);
            int sz0 = (kb + cprow0 < kvhi) ? 16 : 0;
            int sz1 = (kb + cprow1 < kvhi) ? 16 : 0;
            CP_ASYNC(dbase + cpoff0, g + (size_t)kb * DIM + cpg0, sz0);
            CP_ASYNC(dbase + cpoff1, g + (size_t)kb * DIM + cpg1, sz1);
        }
        CP_COMMIT();
    }

    for (int it = 0; it < nIter; it++) {
        const int kb = kvlo + it * BN;
        if (it + 1 < nIter) {
            const int kn = kb + BN;
            uint32_t nbase = sb + S_KV + (uint32_t)(((it + 1) & 1) * KV_STAGE);
            #pragma unroll
            for (int t2 = 0; t2 < 2; t2++) {
                const __half* g = (t2 == 0) ? gKH : gVH;
                uint32_t dbase = nbase + (uint32_t)(t2 * 8192);
                int sz0 = (kn + cprow0 < kvhi) ? 16 : 0;
                int sz1 = (kn + cprow1 < kvhi) ? 16 : 0;
                CP_ASYNC(dbase + cpoff0, g + (size_t)kn * DIM + cpg0, sz0);
                CP_ASYNC(dbase + cpoff1, g + (size_t)kn * DIM + cpg1, sz1);
            }
            CP_COMMIT();
            CP_WAIT1();
        } else {
            CP_WAIT0();
        }
        __syncthreads();

        const uint32_t kvb = sb + S_KV + (uint32_t)((it & 1) * KV_STAGE);
        const uint32_t kbase = kvb + T_KH + krow4;
        const uint32_t vbase = kvb + T_VH + vrow4;

        // ---- MMA1: S = Qh Kh^T + Ql Kh^T ----
        float s[8][4];
        #pragma unroll
        for (int n = 0; n < 8; n++)
            #pragma unroll
            for (int e = 0; e < 4; e++) s[n][e] = 0.f;

        #pragma unroll
        for (int c = 0; c < 4; c++) {
            uint32_t qh[4], ql[4];
            uint32_t qaddr = sb + S_QH + qrow + (uint32_t)(((qcc + 2 * c) ^ swz) << 4);
            ldsm_x4(qh[0], qh[1], qh[2], qh[3], qaddr);
            ldsm_x4(ql[0], ql[1], ql[2], ql[3], qaddr + 16384);
            const uint32_t kchunk = (uint32_t)(((khalf + 2 * c) ^ swz) << 4);
            #pragma unroll
            for (int jp = 0; jp < 4; jp++) {
                uint32_t kh[4];
                uint32_t kaddr = kbase + (uint32_t)(jp * 2048) + kchunk;
                ldsm_x4(kh[0], kh[1], kh[2], kh[3], kaddr);
                mma_f16(s[2 * jp],     qh, kh);
                mma_f16(s[2 * jp],     ql, kh);
                mma_f16(s[2 * jp + 1], qh, kh + 2);
                mma_f16(s[2 * jp + 1], ql, kh + 2);
            }
        }

        // ---- boundary tiles only: clamp invalid entries ----
        if (kb < lomax || kb + BN > himin) {
            const int clo0 = lo0 - kb, chi0 = hi0 - kb;
            const int clo1 = lo1 - kb, chi1 = hi1 - kb;
            #pragma unroll
            for (int j = 0; j < 8; j++) {
                int cb = j * 8 + (lane & 3) * 2;
                if (cb < clo0     || cb >= chi0)     s[j][0] = MASKV;
                if (cb + 1 < clo0 || cb + 1 >= chi0) s[j][1] = MASKV;
                if (cb < clo1     || cb >= chi1)     s[j][2] = MASKV;
                if (cb + 1 < clo1 || cb + 1 >= chi1) s[j][3] = MASKV;
            }
        }

        // ---- online softmax (unconditional) ----
        float mt0 = -1e30f, mt1 = -1e30f;
        #pragma unroll
        for (int j = 0; j < 8; j++) {
            mt0 = fmaxf(mt0, fmaxf(s[j][0], s[j][1]));
            mt1 = fmaxf(mt1, fmaxf(s[j][2], s[j][3]));
        }
        mt0 = fmaxf(mt0, __shfl_xor_sync(0xffffffffu, mt0, 1));
        mt0 = fmaxf(mt0, __shfl_xor_sync(0xffffffffu, mt0, 2));
        mt1 = fmaxf(mt1, __shfl_xor_sync(0xffffffffu, mt1, 1));
        mt1 = fmaxf(mt1, __shfl_xor_sync(0xffffffffu, mt1, 2));

        float mn0 = fmaxf(m0r, mt0), mn1 = fmaxf(m1r, mt1);
        float a0 = ex2(m0r - mn0), a1 = ex2(m1r - mn1);
        m0r = mn0; m1r = mn1;
        #pragma unroll
        for (int n = 0; n < 8; n++) {
            o[n][0] *= a0; o[n][1] *= a0;
            o[n][2] *= a1; o[n][3] *= a1;
        }

        // ---- fused exp2 + pack + MMA2: O += P Vh ----
        float ps0 = 0.f, ps1 = 0.f;
        #pragma unroll
        for (int c = 0; c < 4; c++) {
            uint32_t pa[4];
            #pragma unroll
            for (int jj = 0; jj < 2; jj++) {
                int j = 2 * c + jj;
                float p0 = ex2(s[j][0] - mn0);
                float p1 = ex2(s[j][1] - mn0);
                float p2 = ex2(s[j][2] - mn1);
                float p3 = ex2(s[j][3] - mn1);
                ps0 += p0 + p1; ps1 += p2 + p3;
                pa[2 * jj]     = packh2(p0, p1);
                pa[2 * jj + 1] = packh2(p2, p3);
            }
            uint32_t vcbase = vbase + (uint32_t)(c * 2048);
            #pragma unroll
            for (int np = 0; np < 4; np++) {
                uint32_t vh[4];
                uint32_t vaddr = vcbase + (uint32_t)(((2 * np + vnsel) ^ swz) << 4);
                ldsm_x4t(vh[0], vh[1], vh[2], vh[3], vaddr);
                mma_f16(o[2 * np],     pa, vh);
                mma_f16(o[2 * np + 1], pa, vh + 2);
            }
        }
        l0r = l0r * a0 + ps0;
        l1r = l1r * a1 + ps1;
        __syncthreads();
    }

    // ---- epilogue ----
    l0r += __shfl_xor_sync(0xffffffffu, l0r, 1);
    l0r += __shfl_xor_sync(0xffffffffu, l0r, 2);
    l1r += __shfl_xor_sync(0xffffffffu, l1r, 1);
    l1r += __shfl_xor_sync(0xffffffffu, l1r, 2);
    float inv0 = l0r > 0.f ? 1.f / l0r : 0.f;
    float inv1 = l1r > 0.f ? 1.f / l1r : 0.f;

    const int t0 = q0 + r0, t1 = t0 + 8;
    const int colb = (lane & 3) * 2;
    if (t0 < T) {
        float* op = out + (size_t)t0 * (HEADS * DIM) + h * DIM + colb;
        #pragma unroll
        for (int n = 0; n < 8; n++)
            *(float2*)(op + n * 8) = make_float2(o[n][0] * inv0, o[n][1] * inv0);
    }
    if (t1 < T) {
        float* op = out + (size_t)t1 * (HEADS * DIM) + h * DIM + colb;
        #pragma unroll
        for (int n = 0; n < 8; n++)
            *(float2*)(op + n * 8) = make_float2(o[n][2] * inv1, o[n][3] * inv1);
    }
}

// ---------------- launch ----------------
extern "C" void kernel_launch(void* const* d_in, const int* in_sizes, int n_in,
                              void* d_out, int out_size)
{
    const float* qkv = (const float*)d_in[0];
    const int*   cu  = (const int*)d_in[1];
    const int T    = in_sizes[0] / (3 * HEADS * DIM);
    const int nseg = in_sizes[1] - 1;

    static bool init = false;
    if (!init) {
        cudaFuncSetAttribute(attn_main, cudaFuncAttributeMaxDynamicSharedMemorySize, SMEM_BYTES);
        init = true;
    }

    prep<<<(T * HEADS * 16 + 255) / 256, 256>>>(qkv, T);
    attn_main<<<dim3((T + BM - 1) / BM, HEADS), NT, SMEM_BYTES>>>(cu, nseg, T, (float*)d_out);
}

// round 9
// speedup vs baseline: 7.9152x; 1.2631x over previous
#include <cuda_runtime.h>
#include <cuda_fp16.h>
#include <cstdint>

#define HEADS 8
#define DIM   64
#define TMAXP 4096
#define BM    128
#define BN    64
#define NT    256

// smem layout (bytes): swizzled 128B rows
#define S_QH 0
#define S_KV 16384            // + stage*KV_STAGE, 3 stages
#define KV_STAGE 16384
#define T_KH 0
#define T_VH 8192
#define S_RS 65536
#define S_RE 66048
#define SMEM_BYTES 66560

#define MASKV -3.0e38f

// ---------------- scratch (fp16) ----------------
__device__ __align__(16) __half g_Qh[(size_t)HEADS * TMAXP * DIM];
__device__ __align__(16) __half g_Kh[(size_t)HEADS * TMAXP * DIM];
__device__ __align__(16) __half g_Vh[(size_t)HEADS * TMAXP * DIM];

// ---------------- helpers ----------------
__device__ __forceinline__ float ex2(float x) {
    float r;
    asm("ex2.approx.ftz.f32 %0, %1;" : "=f"(r) : "f"(x));
    return r;
}
__device__ __forceinline__ uint32_t smem_u32(const void* p) {
    uint32_t a;
    asm("{ .reg .u64 t; cvta.to.shared.u64 t, %1; cvt.u32.u64 %0, t; }" : "=r"(a) : "l"(p));
    return a;
}
__device__ __forceinline__ void ldsm_x4(uint32_t& r0, uint32_t& r1, uint32_t& r2, uint32_t& r3, uint32_t a) {
    asm volatile("ldmatrix.sync.aligned.m8n8.x4.shared.b16 {%0,%1,%2,%3}, [%4];"
                 : "=r"(r0), "=r"(r1), "=r"(r2), "=r"(r3) : "r"(a));
}
__device__ __forceinline__ void ldsm_x4t(uint32_t& r0, uint32_t& r1, uint32_t& r2, uint32_t& r3, uint32_t a) {
    asm volatile("ldmatrix.sync.aligned.m8n8.x4.trans.shared.b16 {%0,%1,%2,%3}, [%4];"
                 : "=r"(r0), "=r"(r1), "=r"(r2), "=r"(r3) : "r"(a));
}
__device__ __forceinline__ void mma_f16(float* c, const uint32_t* a, const uint32_t* b) {
    asm volatile("mma.sync.aligned.m16n8k16.row.col.f32.f16.f16.f32 "
                 "{%0,%1,%2,%3}, {%4,%5,%6,%7}, {%8,%9}, {%0,%1,%2,%3};"
                 : "+f"(c[0]), "+f"(c[1]), "+f"(c[2]), "+f"(c[3])
                 : "r"(a[0]), "r"(a[1]), "r"(a[2]), "r"(a[3]), "r"(b[0]), "r"(b[1]));
}
// pack two floats to fp16x2 (lo = a, hi = b)
__device__ __forceinline__ uint32_t packh2(float a, float b) {
    uint32_t r;
    asm("cvt.rn.f16x2.f32 %0, %1, %2;" : "=r"(r) : "f"(b), "f"(a));
    return r;
}
#define CP_ASYNC(dst, src, sz) \
    asm volatile("cp.async.cg.shared.global [%0], [%1], 16, %2;" :: "r"(dst), "l"(src), "r"(sz))
#define CP_COMMIT() asm volatile("cp.async.commit_group;" ::: "memory")
#define CP_WAIT0()  asm volatile("cp.async.wait_group 0;" ::: "memory")
#define CP_WAIT1()  asm volatile("cp.async.wait_group 1;" ::: "memory")

// ---------------- prep: fp32 qkv -> fp16 (Q scaled, K, V) ----------------
__global__ void prep(const float* __restrict__ qkv, int T) {
    int idx = blockIdx.x * blockDim.x + threadIdx.x;
    if (idx >= T * HEADS * 16) return;
    int d4 = idx & 15;
    int h  = (idx >> 4) & (HEADS - 1);
    int t  = idx >> 7;
    const size_t gin = (size_t)t * 1536 + h * 64 + d4 * 4;
    const float4 q = *(const float4*)(qkv + gin);
    const float4 k = *(const float4*)(qkv + gin + 512);
    const float4 v = *(const float4*)(qkv + gin + 1024);
    size_t base = ((size_t)h * TMAXP + t) * DIM + d4 * 4;
    const float s = 0.125f * 1.4426950408889634f;  // 1/sqrt(64) * log2(e)
    *(uint2*)(g_Qh + base) = make_uint2(packh2(q.x * s, q.y * s), packh2(q.z * s, q.w * s));
    *(uint2*)(g_Kh + base) = make_uint2(packh2(k.x, k.y), packh2(k.z, k.w));
    *(uint2*)(g_Vh + base) = make_uint2(packh2(v.x, v.y), packh2(v.z, v.w));
}

// ---------------- main attention ----------------
__global__ __launch_bounds__(NT, 2)
void attn_main(const int* __restrict__ cu, int nseg, int T, float* __restrict__ out)
{
    extern __shared__ char smem[];
    const uint32_t sb = smem_u32(smem);
    const int tid = threadIdx.x, wid = tid >> 5, lane = tid & 31;
    const int q0 = blockIdx.x * BM;
    const int h  = blockIdx.y;
    int* rs_s = (int*)(smem + S_RS);
    int* re_s = (int*)(smem + S_RE);

    // stage Q tile, swizzled
    {
        const uint4* qh = (const uint4*)(g_Qh + ((size_t)h * TMAXP + q0) * DIM);
        #pragma unroll
        for (int p = 0; p < 4; p++) {
            int i = tid + p * NT;
            int row = i >> 3, c = i & 7;
            uint32_t soff = (uint32_t)(row * 128 + ((c ^ (row & 7)) << 4));
            if (q0 + row < T) *(uint4*)(smem + S_QH + soff) = qh[i];
            else              *(uint4*)(smem + S_QH + soff) = make_uint4(0, 0, 0, 0);
        }
    }
    if (tid < BM) {
        int t = q0 + tid; if (t > T - 1) t = T - 1;
        int s = 0;
        for (int i = 0; i < nseg; i++) if (t >= cu[i]) s = i;
        rs_s[tid] = cu[s]; re_s[tid] = cu[s + 1];
    }
    __syncthreads();
    const int kvlo = rs_s[0];
    const int kvhi = re_s[BM - 1];

    const int m0 = wid * 16;
    const int r0 = m0 + (lane >> 2);
    const int lo0 = rs_s[r0],     hi0 = re_s[r0];
    const int lo1 = rs_s[r0 + 8], hi1 = re_s[r0 + 8];
    const int lomax = lo0 > lo1 ? lo0 : lo1;
    const int himin = hi0 < hi1 ? hi0 : hi1;

    const __half* gKH = g_Kh + (size_t)h * TMAXP * DIM;
    const __half* gVH = g_Vh + (size_t)h * TMAXP * DIM;

    // cp.async staging geometry
    const int cpc   = tid & 7;
    const int cprow0 = tid >> 3;          // 0..31
    const int cprow1 = cprow0 + 32;       // 32..63
    const uint32_t cpoff0 = (uint32_t)(cprow0 * 128 + ((cpc ^ (cprow0 & 7)) << 4));
    const uint32_t cpoff1 = (uint32_t)(cprow1 * 128 + ((cpc ^ (cprow1 & 7)) << 4));
    const int cpg0 = cprow0 * 64 + cpc * 8;
    const int cpg1 = cprow1 * 64 + cpc * 8;

    float m0r = -1e30f, m1r = -1e30f, l0r = 0.f, l1r = 0.f;
    float o[8][4];
    #pragma unroll
    for (int n = 0; n < 8; n++)
        #pragma unroll
        for (int e = 0; e < 4; e++) o[n][e] = 0.f;

    // fragment address invariants
    const int swz = lane & 7;
    const uint32_t qrow = (uint32_t)((m0 + (lane & 15)) * 128);
    const int qcc = lane >> 4;
    const uint32_t krow4 = (uint32_t)((((lane >> 4) * 8) + (lane & 7)) * 128);
    const int khalf = (lane >> 3) & 1;
    const uint32_t vrow4 = (uint32_t)(((((lane >> 3) & 1) * 8) + (lane & 7)) * 128);
    const int vnsel = lane >> 4;

    const uint32_t ones2[2] = { 0x3C003C00u, 0x3C003C00u };  // fp16 1.0 x2

    const int nIter = (kvhi - kvlo + BN - 1) / BN;

    // prologue: stage tiles 0 and 1
    #pragma unroll
    for (int pre = 0; pre < 2; pre++) {
        if (pre < nIter) {
            const int kb = kvlo + pre * BN;
            uint32_t dbase = sb + S_KV + (uint32_t)(pre * KV_STAGE);
            int sz0 = (kb + cprow0 < kvhi) ? 16 : 0;
            int sz1 = (kb + cprow1 < kvhi) ? 16 : 0;
            CP_ASYNC(dbase + T_KH + cpoff0, gKH + (size_t)kb * DIM + cpg0, sz0);
            CP_ASYNC(dbase + T_KH + cpoff1, gKH + (size_t)kb * DIM + cpg1, sz1);
            CP_ASYNC(dbase + T_VH + cpoff0, gVH + (size_t)kb * DIM + cpg0, sz0);
            CP_ASYNC(dbase + T_VH + cpoff1, gVH + (size_t)kb * DIM + cpg1, sz1);
        }
        CP_COMMIT();
    }

    for (int it = 0; it < nIter; it++) {
        const int kb = kvlo + it * BN;

        // wait for tile it (allow 1 group in flight), then sync all warps
        if (it + 1 < nIter) { CP_WAIT1(); } else { CP_WAIT0(); }
        __syncthreads();

        // issue tile it+2 into buffer (it+2)%3 — safe: all warps done reading it
        if (it + 2 < nIter) {
            const int kn = kb + 2 * BN;
            uint32_t dbase = sb + S_KV + (uint32_t)(((it + 2) % 3) * KV_STAGE);
            int sz0 = (kn + cprow0 < kvhi) ? 16 : 0;
            int sz1 = (kn + cprow1 < kvhi) ? 16 : 0;
            CP_ASYNC(dbase + T_KH + cpoff0, gKH + (size_t)kn * DIM + cpg0, sz0);
            CP_ASYNC(dbase + T_KH + cpoff1, gKH + (size_t)kn * DIM + cpg1, sz1);
            CP_ASYNC(dbase + T_VH + cpoff0, gVH + (size_t)kn * DIM + cpg0, sz0);
            CP_ASYNC(dbase + T_VH + cpoff1, gVH + (size_t)kn * DIM + cpg1, sz1);
            CP_COMMIT();
        }

        const uint32_t kvb = sb + S_KV + (uint32_t)((it % 3) * KV_STAGE);
        const uint32_t kbase = kvb + T_KH + krow4;
        const uint32_t vbase = kvb + T_VH + vrow4;

        // ---- MMA1: S = Qh Kh^T ----
        float s[8][4];
        #pragma unroll
        for (int n = 0; n < 8; n++)
            #pragma unroll
            for (int e = 0; e < 4; e++) s[n][e] = 0.f;

        #pragma unroll
        for (int c = 0; c < 4; c++) {
            uint32_t qh[4];
            uint32_t qaddr = sb + S_QH + qrow + (uint32_t)(((qcc + 2 * c) ^ swz) << 4);
            ldsm_x4(qh[0], qh[1], qh[2], qh[3], qaddr);
            const uint32_t kchunk = (uint32_t)(((khalf + 2 * c) ^ swz) << 4);
            #pragma unroll
            for (int jp = 0; jp < 4; jp++) {
                uint32_t kh[4];
                uint32_t kaddr = kbase + (uint32_t)(jp * 2048) + kchunk;
                ldsm_x4(kh[0], kh[1], kh[2], kh[3], kaddr);
                mma_f16(s[2 * jp],     qh, kh);
                mma_f16(s[2 * jp + 1], qh, kh + 2);
            }
        }

        // ---- boundary tiles only: clamp invalid entries ----
        if (kb < lomax || kb + BN > himin) {
            const int clo0 = lo0 - kb, chi0 = hi0 - kb;
            const int clo1 = lo1 - kb, chi1 = hi1 - kb;
            #pragma unroll
            for (int j = 0; j < 8; j++) {
                int cb = j * 8 + (lane & 3) * 2;
                if (cb < clo0     || cb >= chi0)     s[j][0] = MASKV;
                if (cb + 1 < clo0 || cb + 1 >= chi0) s[j][1] = MASKV;
                if (cb < clo1     || cb >= chi1)     s[j][2] = MASKV;
                if (cb + 1 < clo1 || cb + 1 >= chi1) s[j][3] = MASKV;
            }
        }

        // ---- online softmax ----
        float mt0 = -1e30f, mt1 = -1e30f;
        #pragma unroll
        for (int j = 0; j < 8; j++) {
            mt0 = fmaxf(mt0, fmaxf(s[j][0], s[j][1]));
            mt1 = fmaxf(mt1, fmaxf(s[j][2], s[j][3]));
        }
        mt0 = fmaxf(mt0, __shfl_xor_sync(0xffffffffu, mt0, 1));
        mt0 = fmaxf(mt0, __shfl_xor_sync(0xffffffffu, mt0, 2));
        mt1 = fmaxf(mt1, __shfl_xor_sync(0xffffffffu, mt1, 1));
        mt1 = fmaxf(mt1, __shfl_xor_sync(0xffffffffu, mt1, 2));

        float mn0 = fmaxf(m0r, mt0), mn1 = fmaxf(m1r, mt1);
        float a0 = ex2(m0r - mn0), a1 = ex2(m1r - mn1);
        m0r = mn0; m1r = mn1;
        #pragma unroll
        for (int n = 0; n < 8; n++) {
            o[n][0] *= a0; o[n][1] *= a0;
            o[n][2] *= a1; o[n][3] *= a1;
        }

        // ---- fused exp2 + pack + MMA2: O += P Vh, rowsum via ones-MMA ----
        float ls[4] = { 0.f, 0.f, 0.f, 0.f };
        #pragma unroll
        for (int c = 0; c < 4; c++) {
            uint32_t pa[4];
            #pragma unroll
            for (int jj = 0; jj < 2; jj++) {
                int j = 2 * c + jj;
                float p0 = ex2(s[j][0] - mn0);
                float p1 = ex2(s[j][1] - mn0);
                float p2 = ex2(s[j][2] - mn1);
                float p3 = ex2(s[j][3] - mn1);
                pa[2 * jj]     = packh2(p0, p1);
                pa[2 * jj + 1] = packh2(p2, p3);
            }
            mma_f16(ls, pa, ones2);   // row sums of the fp16 P actually used
            uint32_t vcbase = vbase + (uint32_t)(c * 2048);
            #pragma unroll
            for (int np = 0; np < 4; np++) {
                uint32_t vh[4];
                uint32_t vaddr = vcbase + (uint32_t)(((2 * np + vnsel) ^ swz) << 4);
                ldsm_x4t(vh[0], vh[1], vh[2], vh[3], vaddr);
                mma_f16(o[2 * np],     pa, vh);
                mma_f16(o[2 * np + 1], pa, vh + 2);
            }
        }
        l0r = l0r * a0 + ls[0];
        l1r = l1r * a1 + ls[2];
    }

    // ---- epilogue (ls already holds full row sums; no l reduction needed) ----
    float inv0 = l0r > 0.f ? 1.f / l0r : 0.f;
    float inv1 = l1r > 0.f ? 1.f / l1r : 0.f;

    const int t0 = q0 + r0, t1 = t0 + 8;
    const int colb = (lane & 3) * 2;
    if (t0 < T) {
        float* op = out + (size_t)t0 * (HEADS * DIM) + h * DIM + colb;
        #pragma unroll
        for (int n = 0; n < 8; n++)
            *(float2*)(op + n * 8) = make_float2(o[n][0] * inv0, o[n][1] * inv0);
    }
    if (t1 < T) {
        float* op = out + (size_t)t1 * (HEADS * DIM) + h * DIM + colb;
        #pragma unroll
        for (int n = 0; n < 8; n++)
            *(float2*)(op + n * 8) = make_float2(o[n][2] * inv1, o[n][3] * inv1);
    }
}

// ---------------- launch ----------------
extern "C" void kernel_launch(void* const* d_in, const int* in_sizes, int n_in,
                              void* d_out, int out_size)
{
    const float* qkv = (const float*)d_in[0];
    const int*   cu  = (const int*)d_in[1];
    const int T    = in_sizes[0] / (3 * HEADS * DIM);
    const int nseg = in_sizes[1] - 1;

    static bool init = false;
    if (!init) {
        cudaFuncSetAttribute(attn_main, cudaFuncAttributeMaxDynamicSharedMemorySize, SMEM_BYTES);
        init = true;
    }

    prep<<<(T * HEADS * 16 + 255) / 256, 256>>>(qkv, T);
    attn_main<<<dim3((T + BM - 1) / BM, HEADS), NT, SMEM_BYTES>>>(cu, nseg, T, (float*)d_out);
}